// round 8
// baseline (speedup 1.0000x reference)
#include <cuda_runtime.h>
#include <cuda_bf16.h>
#include <math.h>
#include <cstdint>

#define B_ 8
#define S_ 256
#define V_ 32000
#define E_ 512
#define H_ 1024
#define G_ 3072      // 3H
#define T_ 2048      // B*S
#define F_ 1536      // H+E
#define NT_ 250      // V/128 score tiles per row (grid.x)
#define NT2_ 500     // per-row softmax partials (one per 64-wide half tile)
#define GRU_CTAS 128

// ---------------- scratch (static device globals; no allocation) ----------------
__device__ float g_Wpack[(size_t)GRU_CTAS * 1024 * 32];  // per-CTA packed W_hh [c][k][g24(pad32)]
__device__ float g_feat[(size_t)T_ * F_];                // [t][ ctx(1024) | emb(512) ]
__device__ float g_gx[(size_t)T_ * G_];                  // input gates
__device__ __nv_bfloat16 g_embh[(size_t)V_ * E_];        // emb table in bf16
__device__ __nv_bfloat16 g_logbf[(size_t)T_ * E_];       // logits in bf16
__device__ float2 g_part[(size_t)T_ * NT2_];             // per (row, half-tile): (max, sumexp)
__device__ float g_lse[T_];
__device__ float g_hbuf[2 * H_ * B_];                    // ping-pong hidden state [k][b]
__device__ unsigned int g_cnt[S_];                       // per-step barrier counters

// ---------------- packed f32x2 helpers (PTX ISA 8.6, sm_100 family) ----------------
__device__ __forceinline__ void fma2(uint64_t& c, uint64_t a, uint64_t b) {
    asm("fma.rn.f32x2 %0, %1, %2, %0;" : "+l"(c) : "l"(a), "l"(b));
}
__device__ __forceinline__ uint64_t pack_dup(float w) {
    uint64_t r;
    asm("mov.b64 %0, {%1, %1};" : "=l"(r) : "f"(w));
    return r;
}
__device__ __forceinline__ uint64_t pack2(float lo, float hi) {
    uint64_t r;
    asm("mov.b64 %0, {%1, %2};" : "=l"(r) : "f"(lo), "f"(hi));
    return r;
}
__device__ __forceinline__ void unpack2(uint64_t v, float& lo, float& hi) {
    asm("mov.b64 {%0, %1}, %2;" : "=f"(lo), "=f"(hi) : "l"(v));
}

__device__ __forceinline__ uint32_t smem_u32(const void* p) {
    uint32_t a;
    asm("{ .reg .u64 t; cvta.to.shared.u64 t, %1; cvt.u32.u64 %0, t; }" : "=r"(a) : "l"(p));
    return a;
}
__device__ __forceinline__ void cpasync16(uint32_t dst, const void* src) {
    asm volatile("cp.async.cg.shared.global [%0], [%1], 16;" :: "r"(dst), "l"(src));
}
#define CP_COMMIT()  asm volatile("cp.async.commit_group;" ::: "memory")
#define CP_WAIT(n)   asm volatile("cp.async.wait_group %0;" :: "n"(n) : "memory")

// ---------------- K0: pack W_hh per GRU CTA + zero barrier counters ----------------
__global__ void pack_kernel(const float* __restrict__ W_hh) {
    int c = blockIdx.x, tid = threadIdx.x;
    if (c == 0 && tid < S_) g_cnt[tid] = 0u;
    for (int idx = tid; idx < 1024 * 32; idx += 256) {
        int k = idx >> 5, g24 = idx & 31;
        float v = 0.f;
        if (g24 < 24) {
            int gate = g24 >> 3, jj = g24 & 7;
            int g = gate * H_ + c * 8 + jj;
            v = W_hh[(size_t)g * H_ + k];
        }
        g_Wpack[(size_t)c * 32768 + idx] = v;
    }
}

// ---------------- K1: embedding gather into feat[:, H:] ----------------
__global__ void embed_kernel(const int* __restrict__ x, const float* __restrict__ emb_W) {
    int t = blockIdx.x, tid = threadIdx.x;
    int tok = x[t];
    const float4* src = (const float4*)(emb_W + (size_t)tok * E_);
    float4* dst = (float4*)(g_feat + (size_t)t * F_ + H_);
    dst[tid] = src[tid];
}

// ---------------- K2: fp32 -> bf16 convert (emb table) ----------------
__global__ void cvt_kernel(const float* __restrict__ src, __nv_bfloat16* __restrict__ dst) {
    int i = blockIdx.x * blockDim.x + threadIdx.x;   // float4 index
    float4 v = ((const float4*)src)[i];
    ((__nv_bfloat162*)dst)[2 * i]     = __floats2bfloat162_rn(v.x, v.y);
    ((__nv_bfloat162*)dst)[2 * i + 1] = __floats2bfloat162_rn(v.z, v.w);
}

// ---------------- fp32 SIMT GEMM C = A@B^T (128x128x16 tile, f32x2 core) ----------------
template <int EPI>
__global__ void __launch_bounds__(256) gemm_kernel(
    const float* __restrict__ A, int lda,
    const float* __restrict__ Bm, int ldb,
    const float* __restrict__ bias,
    float* __restrict__ C, __nv_bfloat16* __restrict__ Cb, int ldc, int K)
{
    __shared__ float As[16 * 128];
    __shared__ float Bs[16 * 128];
    const int tid = threadIdx.x;
    const int tx = tid & 15, ty = tid >> 4;
    const int m0 = blockIdx.y * 128, n0 = blockIdx.x * 128;

    uint64_t acc[8][4];
#pragma unroll
    for (int i = 0; i < 8; ++i)
#pragma unroll
        for (int j = 0; j < 4; ++j) acc[i][j] = 0ull;

    for (int k0 = 0; k0 < K; k0 += 16) {
#pragma unroll
        for (int r = 0; r < 2; ++r) {
            int idx = tid + r * 256;
            int rr = idx >> 2, q = idx & 3;
            float4 va = *(const float4*)(A + (size_t)(m0 + rr) * lda + k0 + q * 4);
            As[(q * 4 + 0) * 128 + rr] = va.x;
            As[(q * 4 + 1) * 128 + rr] = va.y;
            As[(q * 4 + 2) * 128 + rr] = va.z;
            As[(q * 4 + 3) * 128 + rr] = va.w;
            float4 vb = *(const float4*)(Bm + (size_t)(n0 + rr) * ldb + k0 + q * 4);
            Bs[(q * 4 + 0) * 128 + rr] = vb.x;
            Bs[(q * 4 + 1) * 128 + rr] = vb.y;
            Bs[(q * 4 + 2) * 128 + rr] = vb.z;
            Bs[(q * 4 + 3) * 128 + rr] = vb.w;
        }
        __syncthreads();
#pragma unroll
        for (int kk = 0; kk < 16; ++kk) {
            float a[8], b[8];
            *(float4*)(a)     = *(const float4*)(As + kk * 128 + ty * 8);
            *(float4*)(a + 4) = *(const float4*)(As + kk * 128 + ty * 8 + 4);
            *(float4*)(b)     = *(const float4*)(Bs + kk * 128 + tx * 8);
            *(float4*)(b + 4) = *(const float4*)(Bs + kk * 128 + tx * 8 + 4);
            uint64_t bb[4];
#pragma unroll
            for (int j = 0; j < 4; ++j) bb[j] = pack2(b[2 * j], b[2 * j + 1]);
#pragma unroll
            for (int i = 0; i < 8; ++i) {
                uint64_t aa = pack_dup(a[i]);
#pragma unroll
                for (int j = 0; j < 4; ++j) fma2(acc[i][j], aa, bb[j]);
            }
        }
        __syncthreads();
    }

    float bn[8];
#pragma unroll
    for (int j = 0; j < 8; ++j) bn[j] = bias[n0 + tx * 8 + j];
#pragma unroll
    for (int i = 0; i < 8; ++i) {
        int row = m0 + ty * 8 + i;
        float c8[8];
#pragma unroll
        for (int j = 0; j < 4; ++j) unpack2(acc[i][j], c8[2 * j], c8[2 * j + 1]);
        if (EPI == 0) {
            float* cp = C + (size_t)row * ldc + n0 + tx * 8;
#pragma unroll
            for (int j4 = 0; j4 < 8; j4 += 4) {
                float4 v;
                v.x = c8[j4 + 0] + bn[j4 + 0];
                v.y = c8[j4 + 1] + bn[j4 + 1];
                v.z = c8[j4 + 2] + bn[j4 + 2];
                v.w = c8[j4 + 3] + bn[j4 + 3];
                *(float4*)(cp + j4) = v;
            }
        } else {
            float v[8];
#pragma unroll
            for (int j = 0; j < 8; ++j) v[j] = tanhf(c8[j] + bn[j]);
            __nv_bfloat162* cp = (__nv_bfloat162*)(Cb + (size_t)row * ldc + n0 + tx * 8);
            cp[0] = __floats2bfloat162_rn(v[0], v[1]);
            cp[1] = __floats2bfloat162_rn(v[2], v[3]);
            cp[2] = __floats2bfloat162_rn(v[4], v[5]);
            cp[3] = __floats2bfloat162_rn(v[6], v[7]);
        }
    }
}

// ---------------- K3: persistent GRU (r5 config: f32x2 GEMV + red/acquire barrier) ----------------
__global__ void __launch_bounds__(256, 1) gru_kernel(const int* __restrict__ x,
                                                     const float* __restrict__ b_hh) {
    __shared__ float h_s[H_ * B_];        // [k][b]  32 KB
    __shared__ float red[24 * 8 * 8];     // [g24][kc][b]
    __shared__ float gh_s[24 * 8];        // [g24][b]
    const int c = blockIdx.x, tid = threadIdx.x;
    const int j0 = c * 8;
    const int g24 = tid % 24, kc = tid / 24;   // valid for tid < 192

    const int jj = tid >> 3, bb = tid & 7;
    const int j = j0 + jj;
    float bh0 = 0.f, bh1 = 0.f, bh2 = 0.f;
    if (tid < 64) { bh0 = b_hh[j]; bh1 = b_hh[H_ + j]; bh2 = b_hh[2 * H_ + j]; }

    unsigned int* cnt;
    {
        unsigned int* base;
        asm("mov.u64 %0, g_cnt;" : "=l"(base));
        cnt = base;
    }

    for (int s = 0; s < S_; ++s) {
        const int p = s & 1;

        // prefetch this step's gx / mask (gate threads)
        float xr = 0.f, xz = 0.f, xn = 0.f;
        int msk = 0, tix = 0;
        if (tid < 64) {
            tix = bb * S_ + s;
            const float* gxr = g_gx + (size_t)tix * G_;
            xr = __ldcg(gxr + j);
            xz = __ldcg(gxr + H_ + j);
            xn = __ldcg(gxr + 2 * H_ + j);
            msk = (__ldg(x + tix) == 0);           // PAD
        }

        if (s == 0) {
            for (int i = tid; i < H_ * B_; i += 256) h_s[i] = 0.f;
        } else {
            const float4* src = (const float4*)(g_hbuf + p * H_ * B_);
            float4* dst = (float4*)h_s;
#pragma unroll
            for (int r = 0; r < 8; ++r) dst[tid + r * 256] = __ldcg(src + tid + r * 256);
        }
        __syncthreads();

        if (tid < 192) {
            uint64_t a0 = 0ull, a1 = 0ull, a2 = 0ull, a3 = 0ull;
            const float* wp = g_Wpack + ((size_t)c * 1024 + kc * 128) * 32 + g24;
            const ulonglong2* h8 = (const ulonglong2*)h_s + kc * 128 * 2;
#pragma unroll 4
            for (int k = 0; k < 128; ++k) {
                uint64_t ww = pack_dup(wp[k * 32]);
                ulonglong2 u = h8[2 * k];
                ulonglong2 v = h8[2 * k + 1];
                fma2(a0, ww, u.x); fma2(a1, ww, u.y);
                fma2(a2, ww, v.x); fma2(a3, ww, v.y);
            }
            float* rp = red + (g24 * 8 + kc) * 8;
            unpack2(a0, rp[0], rp[1]);
            unpack2(a1, rp[2], rp[3]);
            unpack2(a2, rp[4], rp[5]);
            unpack2(a3, rp[6], rp[7]);
        }
        __syncthreads();
        if (tid < 192) {
            int gg = tid % 24, b = tid / 24;
            float v = 0.f;
#pragma unroll
            for (int q = 0; q < 8; ++q) v += red[(gg * 8 + q) * 8 + b];
            gh_s[gg * 8 + b] = v;
        }
        __syncthreads();
        if (tid < 64) {
            float hr = gh_s[(0 * 8 + jj) * 8 + bb] + bh0;
            float hz = gh_s[(1 * 8 + jj) * 8 + bb] + bh1;
            float hn = gh_s[(2 * 8 + jj) * 8 + bb] + bh2;
            float r = 1.f / (1.f + __expf(-(xr + hr)));
            float z = 1.f / (1.f + __expf(-(xz + hz)));
            float n = tanhf(xn + r * hn);
            float hold = h_s[j * 8 + bb];
            float hnew = (1.f - z) * n + z * hold;
            float hout = msk ? hold : hnew;
            g_hbuf[(p ^ 1) * H_ * B_ + j * 8 + bb] = hout;
            g_feat[(size_t)tix * F_ + j] = msk ? 0.f : hout;
        }
        if (s < S_ - 1) {
            __syncthreads();
            if (tid == 0) {
                asm volatile("red.release.gpu.global.add.u32 [%0], 1;"
                             :: "l"(cnt + s) : "memory");
                unsigned int v;
                do {
                    asm volatile("ld.acquire.gpu.global.u32 %0, [%1];"
                                 : "=r"(v) : "l"(cnt + s) : "memory");
                } while (v < (unsigned)GRU_CTAS);
            }
            __syncthreads();
        }
    }
}

// ---------------- K5: HMMA bf16 scores GEMM v3 (cp.async 2-stage, K=32 chunks) ----------------
__device__ __forceinline__ void mma16816(float* c, const uint32_t* a, uint32_t b0, uint32_t b1) {
    asm volatile(
        "mma.sync.aligned.m16n8k16.row.col.f32.bf16.bf16.f32 "
        "{%0,%1,%2,%3}, {%4,%5,%6,%7}, {%8,%9}, {%0,%1,%2,%3};"
        : "+f"(c[0]), "+f"(c[1]), "+f"(c[2]), "+f"(c[3])
        : "r"(a[0]), "r"(a[1]), "r"(a[2]), "r"(a[3]), "r"(b0), "r"(b1));
}

#define SCLDP 40                      // padded row length (bf16) for a 32-wide chunk
#define SCSTG (128 * SCLDP * 2)       // 10240 B per matrix per stage
#define SC_SMEM (4 * SCSTG)           // A0 A1 B0 B1 = 40960 B
#define NCH (E_ / 32)                 // 16 chunks

__global__ void __launch_bounds__(256) scores_kernel(
    const __nv_bfloat16* __restrict__ Abf,   // [T][E]
    const __nv_bfloat16* __restrict__ Bbf,   // [V][E]
    float* __restrict__ out, float2* __restrict__ part)
{
    extern __shared__ char smem[];
    const uint32_t sb = smem_u32(smem);
    const int tid = threadIdx.x, wid = tid >> 5, lane = tid & 31;
    const int m0 = blockIdx.y * 128, n0 = blockIdx.x * 128;
    const int mi = wid >> 1, nj = wid & 1;    // warp grid 4 (m) x 2 (n)
    const int qr = lane >> 2, qc = lane & 3;  // quad row / col-in-quad

    // issue one 32-wide K chunk (A + B) into stage b
    auto issue = [&](int ch, int b) {
        const int k0 = ch * 32;
#pragma unroll
        for (int i = 0; i < 2; ++i) {
            int u = tid + i * 256;
            int r = u >> 2, cc = u & 3;                 // 4 x 16B per 32-wide row
            uint32_t soff = (uint32_t)(r * SCLDP + cc * 8) * 2;
            cpasync16(sb + b * SCSTG + soff,
                      Abf + (size_t)(m0 + r) * E_ + k0 + cc * 8);
            cpasync16(sb + 2 * SCSTG + b * SCSTG + soff,
                      Bbf + (size_t)(n0 + r) * E_ + k0 + cc * 8);
        }
        CP_COMMIT();
    };

    float acc[2][8][4];
#pragma unroll
    for (int ms = 0; ms < 2; ++ms)
#pragma unroll
        for (int ns = 0; ns < 8; ++ns)
#pragma unroll
            for (int q = 0; q < 4; ++q) acc[ms][ns][q] = 0.f;

    issue(0, 0);
    issue(1, 1);

    for (int ch = 0; ch < NCH; ++ch) {
        const int b = ch & 1;
        if (ch < NCH - 1) { CP_WAIT(1); }   // chunk ch landed; ch+1 may still be in flight
        else             { CP_WAIT(0); }
        __syncthreads();
        const __nv_bfloat16* As = (const __nv_bfloat16*)(smem + b * SCSTG);
        const __nv_bfloat16* Bs = (const __nv_bfloat16*)(smem + 2 * SCSTG + b * SCSTG);
#pragma unroll
        for (int kk = 0; kk < 32; kk += 16) {
            int ak = kk + qc * 2;
            uint32_t a[2][4];
#pragma unroll
            for (int ms = 0; ms < 2; ++ms) {
                const __nv_bfloat16* ap = As + (size_t)(mi * 32 + ms * 16 + qr) * SCLDP + ak;
                a[ms][0] = *(const uint32_t*)(ap);
                a[ms][1] = *(const uint32_t*)(ap + 8 * SCLDP);
                a[ms][2] = *(const uint32_t*)(ap + 8);
                a[ms][3] = *(const uint32_t*)(ap + 8 * SCLDP + 8);
            }
#pragma unroll
            for (int ns = 0; ns < 8; ++ns) {
                const __nv_bfloat16* bp = Bs + (size_t)(nj * 64 + ns * 8 + qr) * SCLDP + ak;
                uint32_t b0 = *(const uint32_t*)(bp);
                uint32_t b1 = *(const uint32_t*)(bp + 8);
                mma16816(acc[0][ns], a[0], b0, b1);
                mma16816(acc[1][ns], a[1], b0, b1);
            }
        }
        __syncthreads();                     // stage b fully consumed
        if (ch + 2 < NCH) issue(ch + 2, b);  // refill the stage just freed
    }

    // ---- epilogue: store + per-row (max, sumexp) over this warp's 64-wide slice ----
    const int colbase = n0 + nj * 64;
#pragma unroll
    for (int ms = 0; ms < 2; ++ms) {
#pragma unroll
        for (int half = 0; half < 2; ++half) {
            int row = m0 + mi * 32 + ms * 16 + half * 8 + qr;
            float* op = out + (size_t)row * V_ + colbase + qc * 2;
            float mx = -1e30f;
#pragma unroll
            for (int ns = 0; ns < 8; ++ns) {
                float v0 = acc[ms][ns][half * 2 + 0];
                float v1 = acc[ms][ns][half * 2 + 1];
                *(float2*)(op + ns * 8) = make_float2(v0, v1);
                mx = fmaxf(mx, fmaxf(v0, v1));
            }
            mx = fmaxf(mx, __shfl_xor_sync(0xffffffffu, mx, 1));
            mx = fmaxf(mx, __shfl_xor_sync(0xffffffffu, mx, 2));
            float sm = 0.f;
#pragma unroll
            for (int ns = 0; ns < 8; ++ns) {
                sm += __expf(acc[ms][ns][half * 2 + 0] - mx);
                sm += __expf(acc[ms][ns][half * 2 + 1] - mx);
            }
            sm += __shfl_xor_sync(0xffffffffu, sm, 1);
            sm += __shfl_xor_sync(0xffffffffu, sm, 2);
            if (qc == 0)
                part[(size_t)row * NT2_ + blockIdx.x * 2 + nj] = make_float2(mx, sm);
        }
    }
}

// ---------------- K6: combine per-tile softmax partials -> lse per row ----------------
__global__ void lse_kernel() {
    int row = blockIdx.x, lane = threadIdx.x;
    float m = -1e30f, s = 0.f;
    for (int i = lane; i < NT2_; i += 32) {
        float2 p = g_part[(size_t)row * NT2_ + i];
        if (p.x > m) { s = s * __expf(m - p.x) + p.y; m = p.x; }
        else         { s = s + p.y * __expf(p.x - m); }
    }
#pragma unroll
    for (int o = 16; o > 0; o >>= 1) {
        float mo = __shfl_xor_sync(0xffffffffu, m, o);
        float so = __shfl_xor_sync(0xffffffffu, s, o);
        if (mo > m) { s = s * __expf(m - mo) + so; m = mo; }
        else        { s = s + so * __expf(mo - m); }
    }
    if (lane == 0) g_lse[row] = m + logf(s);
}

// ---------------- K7: out = score - lse[row] ----------------
__global__ void sub_kernel(float* __restrict__ out) {
    size_t idx = (size_t)blockIdx.x * 256 + threadIdx.x;
    int row = (int)(idx / (V_ / 4));
    float4 v = ((float4*)out)[idx];
    float l = g_lse[row];
    v.x -= l; v.y -= l; v.z -= l; v.w -= l;
    ((float4*)out)[idx] = v;
}

// ---------------- launch ----------------
extern "C" void kernel_launch(void* const* d_in, const int* in_sizes, int n_in,
                              void* d_out, int out_size) {
    const int*   x     = (const int*)d_in[0];
    const float* emb_W = (const float*)d_in[1];
    const float* W_ih  = (const float*)d_in[2];
    const float* W_hh  = (const float*)d_in[3];
    const float* b_ih  = (const float*)d_in[4];
    const float* b_hh  = (const float*)d_in[5];
    const float* lin_W = (const float*)d_in[6];
    const float* lin_b = (const float*)d_in[7];
    float* out = (float*)d_out;

    float *feat, *gx;
    __nv_bfloat16 *embh, *logbf;
    float2* part;
    cudaGetSymbolAddress((void**)&feat,  g_feat);
    cudaGetSymbolAddress((void**)&gx,    g_gx);
    cudaGetSymbolAddress((void**)&embh,  g_embh);
    cudaGetSymbolAddress((void**)&logbf, g_logbf);
    cudaGetSymbolAddress((void**)&part,  g_part);

    cudaFuncSetAttribute(scores_kernel, cudaFuncAttributeMaxDynamicSharedMemorySize, SC_SMEM);

    pack_kernel<<<GRU_CTAS, 256>>>(W_hh);
    embed_kernel<<<T_, 128>>>(x, emb_W);
    cvt_kernel<<<(V_ * E_ / 4) / 256, 256>>>(emb_W, embh);   // emb table -> bf16
    // gx = emb @ W_ih^T + b_ih
    gemm_kernel<0><<<dim3(G_ / 128, T_ / 128), 256>>>(feat + H_, F_, W_ih, E_, b_ih,
                                                      gx, nullptr, G_, E_);
    gru_kernel<<<GRU_CTAS, 256>>>(x, b_hh);
    // logits = tanh(feat @ lin_W^T + lin_b) -> bf16
    gemm_kernel<1><<<dim3(E_ / 128, T_ / 128), 256>>>(feat, F_, lin_W, F_, lin_b,
                                                      nullptr, logbf, E_, F_);
    // scores = logits_bf16 @ emb_bf16^T (HMMA, cp.async pipelined) + fused partials
    scores_kernel<<<dim3(NT_, T_ / 128), 256, SC_SMEM>>>(logbf, embh, out, part);
    lse_kernel<<<T_, 32>>>();
    sub_kernel<<<(T_ * (V_ / 4)) / 256, 256>>>(out);
}

// round 9
// speedup vs baseline: 1.0438x; 1.0438x over previous
#include <cuda_runtime.h>
#include <cuda_bf16.h>
#include <math.h>
#include <cstdint>

#define B_ 8
#define S_ 256
#define V_ 32000
#define E_ 512
#define H_ 1024
#define G_ 3072      // 3H
#define T_ 2048      // B*S
#define F_ 1536      // H+E
#define NT_ 250      // V/128 score tiles per row (grid.x)
#define NT2_ 500     // per-row softmax partials (one per 64-wide half tile)
#define GRU_CTAS 128

// ---------------- scratch (static device globals; no allocation) ----------------
__device__ float g_Wpack[(size_t)GRU_CTAS * 1024 * 32];  // per-CTA packed W_hh [c][k][g24(pad32)]
__device__ float g_feat[(size_t)T_ * F_];                // [t][ ctx(1024) | emb(512) ]
__device__ float g_gx[(size_t)T_ * G_];                  // input gates
__device__ __nv_bfloat16 g_embh[(size_t)V_ * E_];        // emb table in bf16
__device__ __nv_bfloat16 g_logbf[(size_t)T_ * E_];       // logits in bf16
__device__ float2 g_part[(size_t)T_ * NT2_];             // per (row, half-tile): (max, sumexp)
__device__ float g_lse[T_];
__device__ float g_hbuf[2 * H_ * B_];                    // ping-pong hidden state [k][b]
__device__ unsigned int g_cnt[S_];                       // per-step barrier counters

// ---------------- packed f32x2 helpers (PTX ISA 8.6, sm_100 family) ----------------
__device__ __forceinline__ void fma2(uint64_t& c, uint64_t a, uint64_t b) {
    asm("fma.rn.f32x2 %0, %1, %2, %0;" : "+l"(c) : "l"(a), "l"(b));
}
__device__ __forceinline__ uint64_t pack_dup(float w) {
    uint64_t r;
    asm("mov.b64 %0, {%1, %1};" : "=l"(r) : "f"(w));
    return r;
}
__device__ __forceinline__ uint64_t pack2(float lo, float hi) {
    uint64_t r;
    asm("mov.b64 %0, {%1, %2};" : "=l"(r) : "f"(lo), "f"(hi));
    return r;
}
__device__ __forceinline__ void unpack2(uint64_t v, float& lo, float& hi) {
    asm("mov.b64 {%0, %1}, %2;" : "=f"(lo), "=f"(hi) : "l"(v));
}

__device__ __forceinline__ uint32_t smem_u32(const void* p) {
    uint32_t a;
    asm("{ .reg .u64 t; cvta.to.shared.u64 t, %1; cvt.u32.u64 %0, t; }" : "=r"(a) : "l"(p));
    return a;
}
__device__ __forceinline__ void ldsm4(uint32_t& r0, uint32_t& r1, uint32_t& r2, uint32_t& r3,
                                      uint32_t addr) {
    asm volatile("ldmatrix.sync.aligned.m8n8.x4.shared.b16 {%0,%1,%2,%3}, [%4];"
                 : "=r"(r0), "=r"(r1), "=r"(r2), "=r"(r3) : "r"(addr));
}

// ---------------- K0: pack W_hh per GRU CTA + zero barrier counters ----------------
__global__ void pack_kernel(const float* __restrict__ W_hh) {
    int c = blockIdx.x, tid = threadIdx.x;
    if (c == 0 && tid < S_) g_cnt[tid] = 0u;
    for (int idx = tid; idx < 1024 * 32; idx += 256) {
        int k = idx >> 5, g24 = idx & 31;
        float v = 0.f;
        if (g24 < 24) {
            int gate = g24 >> 3, jj = g24 & 7;
            int g = gate * H_ + c * 8 + jj;
            v = W_hh[(size_t)g * H_ + k];
        }
        g_Wpack[(size_t)c * 32768 + idx] = v;
    }
}

// ---------------- K1: embedding gather into feat[:, H:] ----------------
__global__ void embed_kernel(const int* __restrict__ x, const float* __restrict__ emb_W) {
    int t = blockIdx.x, tid = threadIdx.x;
    int tok = x[t];
    const float4* src = (const float4*)(emb_W + (size_t)tok * E_);
    float4* dst = (float4*)(g_feat + (size_t)t * F_ + H_);
    dst[tid] = src[tid];
}

// ---------------- K2: fp32 -> bf16 convert (emb table) ----------------
__global__ void cvt_kernel(const float* __restrict__ src, __nv_bfloat16* __restrict__ dst) {
    int i = blockIdx.x * blockDim.x + threadIdx.x;   // float4 index
    float4 v = ((const float4*)src)[i];
    ((__nv_bfloat162*)dst)[2 * i]     = __floats2bfloat162_rn(v.x, v.y);
    ((__nv_bfloat162*)dst)[2 * i + 1] = __floats2bfloat162_rn(v.z, v.w);
}

// ---------------- fp32 SIMT GEMM C = A@B^T (128x128x16 tile, f32x2 core) ----------------
template <int EPI>
__global__ void __launch_bounds__(256) gemm_kernel(
    const float* __restrict__ A, int lda,
    const float* __restrict__ Bm, int ldb,
    const float* __restrict__ bias,
    float* __restrict__ C, __nv_bfloat16* __restrict__ Cb, int ldc, int K)
{
    __shared__ float As[16 * 128];
    __shared__ float Bs[16 * 128];
    const int tid = threadIdx.x;
    const int tx = tid & 15, ty = tid >> 4;
    const int m0 = blockIdx.y * 128, n0 = blockIdx.x * 128;

    uint64_t acc[8][4];
#pragma unroll
    for (int i = 0; i < 8; ++i)
#pragma unroll
        for (int j = 0; j < 4; ++j) acc[i][j] = 0ull;

    for (int k0 = 0; k0 < K; k0 += 16) {
#pragma unroll
        for (int r = 0; r < 2; ++r) {
            int idx = tid + r * 256;
            int rr = idx >> 2, q = idx & 3;
            float4 va = *(const float4*)(A + (size_t)(m0 + rr) * lda + k0 + q * 4);
            As[(q * 4 + 0) * 128 + rr] = va.x;
            As[(q * 4 + 1) * 128 + rr] = va.y;
            As[(q * 4 + 2) * 128 + rr] = va.z;
            As[(q * 4 + 3) * 128 + rr] = va.w;
            float4 vb = *(const float4*)(Bm + (size_t)(n0 + rr) * ldb + k0 + q * 4);
            Bs[(q * 4 + 0) * 128 + rr] = vb.x;
            Bs[(q * 4 + 1) * 128 + rr] = vb.y;
            Bs[(q * 4 + 2) * 128 + rr] = vb.z;
            Bs[(q * 4 + 3) * 128 + rr] = vb.w;
        }
        __syncthreads();
#pragma unroll
        for (int kk = 0; kk < 16; ++kk) {
            float a[8], b[8];
            *(float4*)(a)     = *(const float4*)(As + kk * 128 + ty * 8);
            *(float4*)(a + 4) = *(const float4*)(As + kk * 128 + ty * 8 + 4);
            *(float4*)(b)     = *(const float4*)(Bs + kk * 128 + tx * 8);
            *(float4*)(b + 4) = *(const float4*)(Bs + kk * 128 + tx * 8 + 4);
            uint64_t bb[4];
#pragma unroll
            for (int j = 0; j < 4; ++j) bb[j] = pack2(b[2 * j], b[2 * j + 1]);
#pragma unroll
            for (int i = 0; i < 8; ++i) {
                uint64_t aa = pack_dup(a[i]);
#pragma unroll
                for (int j = 0; j < 4; ++j) fma2(acc[i][j], aa, bb[j]);
            }
        }
        __syncthreads();
    }

    float bn[8];
#pragma unroll
    for (int j = 0; j < 8; ++j) bn[j] = bias[n0 + tx * 8 + j];
#pragma unroll
    for (int i = 0; i < 8; ++i) {
        int row = m0 + ty * 8 + i;
        float c8[8];
#pragma unroll
        for (int j = 0; j < 4; ++j) unpack2(acc[i][j], c8[2 * j], c8[2 * j + 1]);
        if (EPI == 0) {
            float* cp = C + (size_t)row * ldc + n0 + tx * 8;
#pragma unroll
            for (int j4 = 0; j4 < 8; j4 += 4) {
                float4 v;
                v.x = c8[j4 + 0] + bn[j4 + 0];
                v.y = c8[j4 + 1] + bn[j4 + 1];
                v.z = c8[j4 + 2] + bn[j4 + 2];
                v.w = c8[j4 + 3] + bn[j4 + 3];
                *(float4*)(cp + j4) = v;
            }
        } else {
            float v[8];
#pragma unroll
            for (int j = 0; j < 8; ++j) v[j] = tanhf(c8[j] + bn[j]);
            __nv_bfloat162* cp = (__nv_bfloat162*)(Cb + (size_t)row * ldc + n0 + tx * 8);
            cp[0] = __floats2bfloat162_rn(v[0], v[1]);
            cp[1] = __floats2bfloat162_rn(v[2], v[3]);
            cp[2] = __floats2bfloat162_rn(v[4], v[5]);
            cp[3] = __floats2bfloat162_rn(v[6], v[7]);
        }
    }
}

// ---------------- K3: persistent GRU (r5 config: f32x2 GEMV + red/acquire barrier) ----------------
__global__ void __launch_bounds__(256, 1) gru_kernel(const int* __restrict__ x,
                                                     const float* __restrict__ b_hh) {
    __shared__ float h_s[H_ * B_];        // [k][b]  32 KB
    __shared__ float red[24 * 8 * 8];     // [g24][kc][b]
    __shared__ float gh_s[24 * 8];        // [g24][b]
    const int c = blockIdx.x, tid = threadIdx.x;
    const int j0 = c * 8;
    const int g24 = tid % 24, kc = tid / 24;   // valid for tid < 192

    const int jj = tid >> 3, bb = tid & 7;
    const int j = j0 + jj;
    float bh0 = 0.f, bh1 = 0.f, bh2 = 0.f;
    if (tid < 64) { bh0 = b_hh[j]; bh1 = b_hh[H_ + j]; bh2 = b_hh[2 * H_ + j]; }

    unsigned int* cnt;
    {
        unsigned int* base;
        asm("mov.u64 %0, g_cnt;" : "=l"(base));
        cnt = base;
    }

    for (int s = 0; s < S_; ++s) {
        const int p = s & 1;

        // prefetch this step's gx / mask (gate threads)
        float xr = 0.f, xz = 0.f, xn = 0.f;
        int msk = 0, tix = 0;
        if (tid < 64) {
            tix = bb * S_ + s;
            const float* gxr = g_gx + (size_t)tix * G_;
            xr = __ldcg(gxr + j);
            xz = __ldcg(gxr + H_ + j);
            xn = __ldcg(gxr + 2 * H_ + j);
            msk = (__ldg(x + tix) == 0);           // PAD
        }

        if (s == 0) {
            for (int i = tid; i < H_ * B_; i += 256) h_s[i] = 0.f;
        } else {
            const float4* src = (const float4*)(g_hbuf + p * H_ * B_);
            float4* dst = (float4*)h_s;
#pragma unroll
            for (int r = 0; r < 8; ++r) dst[tid + r * 256] = __ldcg(src + tid + r * 256);
        }
        __syncthreads();

        if (tid < 192) {
            uint64_t a0 = 0ull, a1 = 0ull, a2 = 0ull, a3 = 0ull;
            const float* wp = g_Wpack + ((size_t)c * 1024 + kc * 128) * 32 + g24;
            const ulonglong2* h8 = (const ulonglong2*)h_s + kc * 128 * 2;
#pragma unroll 4
            for (int k = 0; k < 128; ++k) {
                uint64_t ww = pack_dup(wp[k * 32]);
                ulonglong2 u = h8[2 * k];
                ulonglong2 v = h8[2 * k + 1];
                fma2(a0, ww, u.x); fma2(a1, ww, u.y);
                fma2(a2, ww, v.x); fma2(a3, ww, v.y);
            }
            float* rp = red + (g24 * 8 + kc) * 8;
            unpack2(a0, rp[0], rp[1]);
            unpack2(a1, rp[2], rp[3]);
            unpack2(a2, rp[4], rp[5]);
            unpack2(a3, rp[6], rp[7]);
        }
        __syncthreads();
        if (tid < 192) {
            int gg = tid % 24, b = tid / 24;
            float v = 0.f;
#pragma unroll
            for (int q = 0; q < 8; ++q) v += red[(gg * 8 + q) * 8 + b];
            gh_s[gg * 8 + b] = v;
        }
        __syncthreads();
        if (tid < 64) {
            float hr = gh_s[(0 * 8 + jj) * 8 + bb] + bh0;
            float hz = gh_s[(1 * 8 + jj) * 8 + bb] + bh1;
            float hn = gh_s[(2 * 8 + jj) * 8 + bb] + bh2;
            float r = 1.f / (1.f + __expf(-(xr + hr)));
            float z = 1.f / (1.f + __expf(-(xz + hz)));
            float n = tanhf(xn + r * hn);
            float hold = h_s[j * 8 + bb];
            float hnew = (1.f - z) * n + z * hold;
            float hout = msk ? hold : hnew;
            g_hbuf[(p ^ 1) * H_ * B_ + j * 8 + bb] = hout;
            g_feat[(size_t)tix * F_ + j] = msk ? 0.f : hout;
        }
        if (s < S_ - 1) {
            __syncthreads();
            if (tid == 0) {
                asm volatile("red.release.gpu.global.add.u32 [%0], 1;"
                             :: "l"(cnt + s) : "memory");
                unsigned int v;
                do {
                    asm volatile("ld.acquire.gpu.global.u32 %0, [%1];"
                                 : "=r"(v) : "l"(cnt + s) : "memory");
                } while (v < (unsigned)GRU_CTAS);
            }
            __syncthreads();
        }
    }
}

// ---------------- K5: HMMA bf16 scores GEMM v4 (static smem + ldmatrix) ----------------
__device__ __forceinline__ void mma16816(float* c, const uint32_t* a, uint32_t b0, uint32_t b1) {
    asm volatile(
        "mma.sync.aligned.m16n8k16.row.col.f32.bf16.bf16.f32 "
        "{%0,%1,%2,%3}, {%4,%5,%6,%7}, {%8,%9}, {%0,%1,%2,%3};"
        : "+f"(c[0]), "+f"(c[1]), "+f"(c[2]), "+f"(c[3])
        : "r"(a[0]), "r"(a[1]), "r"(a[2]), "r"(a[3]), "r"(b0), "r"(b1));
}

#define LDP_ 72   // padded row length (bf16): 144B rows, 16B-aligned, LDSM conflict-free

__global__ void __launch_bounds__(256) scores_kernel(
    const __nv_bfloat16* __restrict__ Abf,   // [T][E]
    const __nv_bfloat16* __restrict__ Bbf,   // [V][E]
    float* __restrict__ out, float2* __restrict__ part)
{
    __shared__ __nv_bfloat16 As[128 * LDP_];
    __shared__ __nv_bfloat16 Bs[128 * LDP_];
    const uint32_t sA = smem_u32(As), sB = smem_u32(Bs);
    const int tid = threadIdx.x, wid = tid >> 5, lane = tid & 31;
    const int m0 = blockIdx.y * 128, n0 = blockIdx.x * 128;
    const int mi = wid >> 1, nj = wid & 1;    // warp grid 4 (m) x 2 (n)
    const int qr = lane >> 2, qc = lane & 3;  // quad row / col-in-quad

    // ldmatrix lane-address components
    const int lrowA = lane & 15, lkA = (lane >> 4) * 8;
    const int lrowB = (lane & 7) + ((lane >> 4) << 3), lkB = ((lane >> 3) & 1) * 8;

    float acc[2][8][4];
#pragma unroll
    for (int ms = 0; ms < 2; ++ms)
#pragma unroll
        for (int ns = 0; ns < 8; ++ns)
#pragma unroll
            for (int q = 0; q < 4; ++q) acc[ms][ns][q] = 0.f;

    for (int k0 = 0; k0 < E_; k0 += 64) {
#pragma unroll
        for (int i = 0; i < 4; ++i) {
            int u = tid + i * 256;
            int r = u >> 3, c = u & 7;             // 8 uint4 per 64-wide row
            *(uint4*)(As + r * LDP_ + c * 8) =
                *(const uint4*)(Abf + (size_t)(m0 + r) * E_ + k0 + c * 8);
            *(uint4*)(Bs + r * LDP_ + c * 8) =
                *(const uint4*)(Bbf + (size_t)(n0 + r) * E_ + k0 + c * 8);
        }
        __syncthreads();
#pragma unroll
        for (int kk = 0; kk < 64; kk += 16) {
            uint32_t a[2][4];
#pragma unroll
            for (int ms = 0; ms < 2; ++ms)
                ldsm4(a[ms][0], a[ms][1], a[ms][2], a[ms][3],
                      sA + (uint32_t)((mi * 32 + ms * 16 + lrowA) * LDP_ + kk + lkA) * 2);
            uint32_t bf[8][2];
#pragma unroll
            for (int np = 0; np < 4; ++np) {
                uint32_t r0, r1, r2, r3;
                ldsm4(r0, r1, r2, r3,
                      sB + (uint32_t)((nj * 64 + np * 16 + lrowB) * LDP_ + kk + lkB) * 2);
                bf[np * 2 + 0][0] = r0; bf[np * 2 + 0][1] = r1;
                bf[np * 2 + 1][0] = r2; bf[np * 2 + 1][1] = r3;
            }
#pragma unroll
            for (int ns = 0; ns < 8; ++ns) {
                mma16816(acc[0][ns], a[0], bf[ns][0], bf[ns][1]);
                mma16816(acc[1][ns], a[1], bf[ns][0], bf[ns][1]);
            }
        }
        __syncthreads();
    }

    // ---- epilogue: store + per-row (max, sumexp) over this warp's 64-wide slice ----
    const int colbase = n0 + nj * 64;
#pragma unroll
    for (int ms = 0; ms < 2; ++ms) {
#pragma unroll
        for (int half = 0; half < 2; ++half) {
            int row = m0 + mi * 32 + ms * 16 + half * 8 + qr;
            float* op = out + (size_t)row * V_ + colbase + qc * 2;
            float mx = -1e30f;
#pragma unroll
            for (int ns = 0; ns < 8; ++ns) {
                float v0 = acc[ms][ns][half * 2 + 0];
                float v1 = acc[ms][ns][half * 2 + 1];
                *(float2*)(op + ns * 8) = make_float2(v0, v1);
                mx = fmaxf(mx, fmaxf(v0, v1));
            }
            mx = fmaxf(mx, __shfl_xor_sync(0xffffffffu, mx, 1));
            mx = fmaxf(mx, __shfl_xor_sync(0xffffffffu, mx, 2));
            float sm = 0.f;
#pragma unroll
            for (int ns = 0; ns < 8; ++ns) {
                sm += __expf(acc[ms][ns][half * 2 + 0] - mx);
                sm += __expf(acc[ms][ns][half * 2 + 1] - mx);
            }
            sm += __shfl_xor_sync(0xffffffffu, sm, 1);
            sm += __shfl_xor_sync(0xffffffffu, sm, 2);
            if (qc == 0)
                part[(size_t)row * NT2_ + blockIdx.x * 2 + nj] = make_float2(mx, sm);
        }
    }
}

// ---------------- K6: combine per-tile softmax partials -> lse per row ----------------
__global__ void lse_kernel() {
    int row = blockIdx.x, lane = threadIdx.x;
    float m = -1e30f, s = 0.f;
    for (int i = lane; i < NT2_; i += 32) {
        float2 p = g_part[(size_t)row * NT2_ + i];
        if (p.x > m) { s = s * __expf(m - p.x) + p.y; m = p.x; }
        else         { s = s + p.y * __expf(p.x - m); }
    }
#pragma unroll
    for (int o = 16; o > 0; o >>= 1) {
        float mo = __shfl_xor_sync(0xffffffffu, m, o);
        float so = __shfl_xor_sync(0xffffffffu, s, o);
        if (mo > m) { s = s * __expf(m - mo) + so; m = mo; }
        else        { s = s + so * __expf(mo - m); }
    }
    if (lane == 0) g_lse[row] = m + logf(s);
}

// ---------------- K7: out = score - lse[row] ----------------
__global__ void sub_kernel(float* __restrict__ out) {
    size_t idx = (size_t)blockIdx.x * 256 + threadIdx.x;
    int row = (int)(idx / (V_ / 4));
    float4 v = ((float4*)out)[idx];
    float l = g_lse[row];
    v.x -= l; v.y -= l; v.z -= l; v.w -= l;
    ((float4*)out)[idx] = v;
}

// ---------------- launch (reordered: gru is the 4th launch -> gets profiled) ----------------
extern "C" void kernel_launch(void* const* d_in, const int* in_sizes, int n_in,
                              void* d_out, int out_size) {
    const int*   x     = (const int*)d_in[0];
    const float* emb_W = (const float*)d_in[1];
    const float* W_ih  = (const float*)d_in[2];
    const float* W_hh  = (const float*)d_in[3];
    const float* b_ih  = (const float*)d_in[4];
    const float* b_hh  = (const float*)d_in[5];
    const float* lin_W = (const float*)d_in[6];
    const float* lin_b = (const float*)d_in[7];
    float* out = (float*)d_out;

    float *feat, *gx;
    __nv_bfloat16 *embh, *logbf;
    float2* part;
    cudaGetSymbolAddress((void**)&feat,  g_feat);
    cudaGetSymbolAddress((void**)&gx,    g_gx);
    cudaGetSymbolAddress((void**)&embh,  g_embh);
    cudaGetSymbolAddress((void**)&logbf, g_logbf);
    cudaGetSymbolAddress((void**)&part,  g_part);

    pack_kernel<<<GRU_CTAS, 256>>>(W_hh);                 // 1
    embed_kernel<<<T_, 128>>>(x, emb_W);                  // 2
    // gx = emb @ W_ih^T + b_ih
    gemm_kernel<0><<<dim3(G_ / 128, T_ / 128), 256>>>(feat + H_, F_, W_ih, E_, b_ih,
                                                      gx, nullptr, G_, E_);   // 3
    gru_kernel<<<GRU_CTAS, 256>>>(x, b_hh);               // 4  <-- profiled launch
    cvt_kernel<<<(V_ * E_ / 4) / 256, 256>>>(emb_W, embh);// 5 (emb table -> bf16; only scores needs it)
    // logits = tanh(feat @ lin_W^T + lin_b) -> bf16
    gemm_kernel<1><<<dim3(E_ / 128, T_ / 128), 256>>>(feat, F_, lin_W, F_, lin_b,
                                                      nullptr, logbf, E_, F_);  // 6
    // scores = logits_bf16 @ emb_bf16^T (HMMA + ldmatrix) + fused partials
    scores_kernel<<<dim3(NT_, T_ / 128), 256>>>(logbf, embh, out, part);        // 7
    lse_kernel<<<T_, 32>>>();                             // 8
    sub_kernel<<<(T_ * (V_ / 4)) / 256, 256>>>(out);      // 9
}

// round 10
// speedup vs baseline: 1.0986x; 1.0525x over previous
#include <cuda_runtime.h>
#include <cuda_bf16.h>
#include <math.h>
#include <cstdint>

#define B_ 8
#define S_ 256
#define V_ 32000
#define E_ 512
#define H_ 1024
#define G_ 3072      // 3H
#define T_ 2048      // B*S
#define F_ 1536      // H+E
#define NT_ 250      // V/128 score tiles per row
#define NT2_ 500     // per-row softmax partials (one per 64-wide half tile)
#define GRU_CTAS 128

// ---------------- scratch (static device globals; no allocation) ----------------
__device__ float g_Wpack[(size_t)GRU_CTAS * 1024 * 32];  // per-CTA packed W_hh [c][k][g24(pad32)]
__device__ float g_feat[(size_t)T_ * F_];                // fp32: only emb cols [H:) used (gemm0)
__device__ __nv_bfloat16 g_featbf[(size_t)T_ * F_];      // bf16 feat: ctx | emb (gemm1h input)
__device__ float g_gx[(size_t)T_ * G_];                  // input gates
__device__ __nv_bfloat16 g_embh[(size_t)V_ * E_];        // emb table in bf16
__device__ __nv_bfloat16 g_linbf[(size_t)E_ * F_];       // lin_W in bf16
__device__ __nv_bfloat16 g_logbf[(size_t)T_ * E_];       // logits in bf16
__device__ float2 g_part[(size_t)T_ * NT2_];             // per (row, half-tile): (max, sumexp)
__device__ float g_lse[T_];
__device__ float g_hbuf[2 * H_ * B_];                    // ping-pong hidden state [k][b] (fp32!)
__device__ unsigned int g_cnt[S_];                       // per-step barrier counters

// ---------------- packed f32x2 helpers (PTX ISA 8.6, sm_100 family) ----------------
__device__ __forceinline__ void fma2(uint64_t& c, uint64_t a, uint64_t b) {
    asm("fma.rn.f32x2 %0, %1, %2, %0;" : "+l"(c) : "l"(a), "l"(b));
}
__device__ __forceinline__ uint64_t pack_dup(float w) {
    uint64_t r;
    asm("mov.b64 %0, {%1, %1};" : "=l"(r) : "f"(w));
    return r;
}
__device__ __forceinline__ uint64_t pack2(float lo, float hi) {
    uint64_t r;
    asm("mov.b64 %0, {%1, %2};" : "=l"(r) : "f"(lo), "f"(hi));
    return r;
}
__device__ __forceinline__ void unpack2(uint64_t v, float& lo, float& hi) {
    asm("mov.b64 {%0, %1}, %2;" : "=f"(lo), "=f"(hi) : "l"(v));
}

__device__ __forceinline__ uint32_t smem_u32(const void* p) {
    uint32_t a;
    asm("{ .reg .u64 t; cvta.to.shared.u64 t, %1; cvt.u32.u64 %0, t; }" : "=r"(a) : "l"(p));
    return a;
}
__device__ __forceinline__ void ldsm4(uint32_t& r0, uint32_t& r1, uint32_t& r2, uint32_t& r3,
                                      uint32_t addr) {
    asm volatile("ldmatrix.sync.aligned.m8n8.x4.shared.b16 {%0,%1,%2,%3}, [%4];"
                 : "=r"(r0), "=r"(r1), "=r"(r2), "=r"(r3) : "r"(addr));
}

// ---------------- K1: fused prep (pack W_hh | embed | cvt embW | cvt linW) ----------------
#define PREP_PACK0    0
#define PREP_EMBED0   GRU_CTAS                        // 128
#define PREP_CVTE0    (PREP_EMBED0 + T_)              // 2176
#define PREP_CVTL0    (PREP_CVTE0 + (V_ * E_ / 4) / 256)   // 2176 + 16000 = 18176
#define PREP_BLOCKS   (PREP_CVTL0 + (E_ * F_ / 4) / 256)   // 18176 + 768 = 18944

__global__ void __launch_bounds__(256) prep_kernel(
    const float* __restrict__ W_hh, const int* __restrict__ x,
    const float* __restrict__ emb_W, const float* __restrict__ lin_W)
{
    const int bid = blockIdx.x, tid = threadIdx.x;
    if (bid < PREP_EMBED0) {
        // ---- pack W_hh per GRU CTA ----
        int c = bid;
        if (c == 0 && tid < S_) g_cnt[tid] = 0u;
        for (int idx = tid; idx < 1024 * 32; idx += 256) {
            int k = idx >> 5, g24 = idx & 31;
            float v = 0.f;
            if (g24 < 24) {
                int gate = g24 >> 3, jj = g24 & 7;
                int g = gate * H_ + c * 8 + jj;
                v = W_hh[(size_t)g * H_ + k];
            }
            g_Wpack[(size_t)c * 32768 + idx] = v;
        }
    } else if (bid < PREP_CVTE0) {
        // ---- embedding gather: fp32 (for gemm0) + bf16 (for gemm1h) ----
        int t = bid - PREP_EMBED0;
        if (tid < 128) {
            int tok = x[t];
            float4 v = ((const float4*)(emb_W + (size_t)tok * E_))[tid];
            ((float4*)(g_feat + (size_t)t * F_ + H_))[tid] = v;
            __nv_bfloat162* d = (__nv_bfloat162*)(g_featbf + (size_t)t * F_ + H_) + 2 * tid;
            d[0] = __floats2bfloat162_rn(v.x, v.y);
            d[1] = __floats2bfloat162_rn(v.z, v.w);
        }
    } else if (bid < PREP_CVTL0) {
        // ---- cvt emb_W -> bf16 ----
        int i = (bid - PREP_CVTE0) * 256 + tid;   // float4 index
        float4 v = ((const float4*)emb_W)[i];
        ((__nv_bfloat162*)g_embh)[2 * i]     = __floats2bfloat162_rn(v.x, v.y);
        ((__nv_bfloat162*)g_embh)[2 * i + 1] = __floats2bfloat162_rn(v.z, v.w);
    } else {
        // ---- cvt lin_W -> bf16 ----
        int i = (bid - PREP_CVTL0) * 256 + tid;   // float4 index
        float4 v = ((const float4*)lin_W)[i];
        ((__nv_bfloat162*)g_linbf)[2 * i]     = __floats2bfloat162_rn(v.x, v.y);
        ((__nv_bfloat162*)g_linbf)[2 * i + 1] = __floats2bfloat162_rn(v.z, v.w);
    }
}

// ---------------- fp32 SIMT GEMM (gemm0 only): gx = emb @ W_ih^T + b_ih ----------------
__global__ void __launch_bounds__(256) gemm_kernel(
    const float* __restrict__ A, int lda,
    const float* __restrict__ Bm, int ldb,
    const float* __restrict__ bias,
    float* __restrict__ C, int ldc, int K)
{
    __shared__ float As[16 * 128];
    __shared__ float Bs[16 * 128];
    const int tid = threadIdx.x;
    const int tx = tid & 15, ty = tid >> 4;
    const int m0 = blockIdx.y * 128, n0 = blockIdx.x * 128;

    uint64_t acc[8][4];
#pragma unroll
    for (int i = 0; i < 8; ++i)
#pragma unroll
        for (int j = 0; j < 4; ++j) acc[i][j] = 0ull;

    for (int k0 = 0; k0 < K; k0 += 16) {
#pragma unroll
        for (int r = 0; r < 2; ++r) {
            int idx = tid + r * 256;
            int rr = idx >> 2, q = idx & 3;
            float4 va = *(const float4*)(A + (size_t)(m0 + rr) * lda + k0 + q * 4);
            As[(q * 4 + 0) * 128 + rr] = va.x;
            As[(q * 4 + 1) * 128 + rr] = va.y;
            As[(q * 4 + 2) * 128 + rr] = va.z;
            As[(q * 4 + 3) * 128 + rr] = va.w;
            float4 vb = *(const float4*)(Bm + (size_t)(n0 + rr) * ldb + k0 + q * 4);
            Bs[(q * 4 + 0) * 128 + rr] = vb.x;
            Bs[(q * 4 + 1) * 128 + rr] = vb.y;
            Bs[(q * 4 + 2) * 128 + rr] = vb.z;
            Bs[(q * 4 + 3) * 128 + rr] = vb.w;
        }
        __syncthreads();
#pragma unroll
        for (int kk = 0; kk < 16; ++kk) {
            float a[8], b[8];
            *(float4*)(a)     = *(const float4*)(As + kk * 128 + ty * 8);
            *(float4*)(a + 4) = *(const float4*)(As + kk * 128 + ty * 8 + 4);
            *(float4*)(b)     = *(const float4*)(Bs + kk * 128 + tx * 8);
            *(float4*)(b + 4) = *(const float4*)(Bs + kk * 128 + tx * 8 + 4);
            uint64_t bb[4];
#pragma unroll
            for (int j = 0; j < 4; ++j) bb[j] = pack2(b[2 * j], b[2 * j + 1]);
#pragma unroll
            for (int i = 0; i < 8; ++i) {
                uint64_t aa = pack_dup(a[i]);
#pragma unroll
                for (int j = 0; j < 4; ++j) fma2(acc[i][j], aa, bb[j]);
            }
        }
        __syncthreads();
    }

    float bn[8];
#pragma unroll
    for (int j = 0; j < 8; ++j) bn[j] = bias[n0 + tx * 8 + j];
#pragma unroll
    for (int i = 0; i < 8; ++i) {
        int row = m0 + ty * 8 + i;
        float c8[8];
#pragma unroll
        for (int j = 0; j < 4; ++j) unpack2(acc[i][j], c8[2 * j], c8[2 * j + 1]);
        float* cp = C + (size_t)row * ldc + n0 + tx * 8;
#pragma unroll
        for (int j4 = 0; j4 < 8; j4 += 4) {
            float4 v;
            v.x = c8[j4 + 0] + bn[j4 + 0];
            v.y = c8[j4 + 1] + bn[j4 + 1];
            v.z = c8[j4 + 2] + bn[j4 + 2];
            v.w = c8[j4 + 3] + bn[j4 + 3];
            *(float4*)(cp + j4) = v;
        }
    }
}

// ---------------- K3: persistent GRU (fp32 recurrence; bf16 feat output) ----------------
__global__ void __launch_bounds__(256, 1) gru_kernel(const int* __restrict__ x,
                                                     const float* __restrict__ b_hh) {
    __shared__ float h_s[H_ * B_];        // [k][b]  32 KB
    __shared__ float red[24 * 8 * 8];     // [g24][kc][b]
    __shared__ float gh_s[24 * 8];        // [g24][b]
    const int c = blockIdx.x, tid = threadIdx.x;
    const int j0 = c * 8;
    const int g24 = tid % 24, kc = tid / 24;   // valid for tid < 192

    const int jj = tid >> 3, bb = tid & 7;
    const int j = j0 + jj;
    float bh0 = 0.f, bh1 = 0.f, bh2 = 0.f;
    if (tid < 64) { bh0 = b_hh[j]; bh1 = b_hh[H_ + j]; bh2 = b_hh[2 * H_ + j]; }

    unsigned int* cnt;
    {
        unsigned int* base;
        asm("mov.u64 %0, g_cnt;" : "=l"(base));
        cnt = base;
    }

    for (int s = 0; s < S_; ++s) {
        const int p = s & 1;

        // prefetch this step's gx / mask (gate threads)
        float xr = 0.f, xz = 0.f, xn = 0.f;
        int msk = 0, tix = 0;
        if (tid < 64) {
            tix = bb * S_ + s;
            const float* gxr = g_gx + (size_t)tix * G_;
            xr = __ldcg(gxr + j);
            xz = __ldcg(gxr + H_ + j);
            xn = __ldcg(gxr + 2 * H_ + j);
            msk = (__ldg(x + tix) == 0);           // PAD
        }

        if (s == 0) {
            for (int i = tid; i < H_ * B_; i += 256) h_s[i] = 0.f;
        } else {
            const float4* src = (const float4*)(g_hbuf + p * H_ * B_);
            float4* dst = (float4*)h_s;
#pragma unroll
            for (int r = 0; r < 8; ++r) dst[tid + r * 256] = __ldcg(src + tid + r * 256);
        }
        __syncthreads();

        if (tid < 192) {
            uint64_t a0 = 0ull, a1 = 0ull, a2 = 0ull, a3 = 0ull;
            const float* wp = g_Wpack + ((size_t)c * 1024 + kc * 128) * 32 + g24;
            const ulonglong2* h8 = (const ulonglong2*)h_s + kc * 128 * 2;
#pragma unroll 4
            for (int k = 0; k < 128; ++k) {
                uint64_t ww = pack_dup(wp[k * 32]);
                ulonglong2 u = h8[2 * k];
                ulonglong2 v = h8[2 * k + 1];
                fma2(a0, ww, u.x); fma2(a1, ww, u.y);
                fma2(a2, ww, v.x); fma2(a3, ww, v.y);
            }
            float* rp = red + (g24 * 8 + kc) * 8;
            unpack2(a0, rp[0], rp[1]);
            unpack2(a1, rp[2], rp[3]);
            unpack2(a2, rp[4], rp[5]);
            unpack2(a3, rp[6], rp[7]);
        }
        __syncthreads();
        if (tid < 192) {
            int gg = tid % 24, b = tid / 24;
            float v = 0.f;
#pragma unroll
            for (int q = 0; q < 8; ++q) v += red[(gg * 8 + q) * 8 + b];
            gh_s[gg * 8 + b] = v;
        }
        __syncthreads();
        if (tid < 64) {
            float hr = gh_s[(0 * 8 + jj) * 8 + bb] + bh0;
            float hz = gh_s[(1 * 8 + jj) * 8 + bb] + bh1;
            float hn = gh_s[(2 * 8 + jj) * 8 + bb] + bh2;
            float r = 1.f / (1.f + __expf(-(xr + hr)));
            float z = 1.f / (1.f + __expf(-(xz + hz)));
            float n = tanhf(xn + r * hn);
            float hold = h_s[j * 8 + bb];
            float hnew = (1.f - z) * n + z * hold;
            float hout = msk ? hold : hnew;
            g_hbuf[(p ^ 1) * H_ * B_ + j * 8 + bb] = hout;       // fp32 recurrence
            g_featbf[(size_t)tix * F_ + j] = __float2bfloat16(msk ? 0.f : hout);
        }
        if (s < S_ - 1) {
            __syncthreads();
            if (tid == 0) {
                asm volatile("red.release.gpu.global.add.u32 [%0], 1;"
                             :: "l"(cnt + s) : "memory");
                unsigned int v;
                do {
                    asm volatile("ld.acquire.gpu.global.u32 %0, [%1];"
                                 : "=r"(v) : "l"(cnt + s) : "memory");
                } while (v < (unsigned)GRU_CTAS);
            }
            __syncthreads();
        }
    }
}

// ---------------- HMMA bf16 GEMM template (ldmatrix mainloop) ----------------
// C = A[M,K] @ B[N,K]^T. EPI 0: tanh(acc+bias) -> bf16 (gemm1h). EPI 1: fp32 + softmax partials (scores).
__device__ __forceinline__ void mma16816(float* c, const uint32_t* a, uint32_t b0, uint32_t b1) {
    asm volatile(
        "mma.sync.aligned.m16n8k16.row.col.f32.bf16.bf16.f32 "
        "{%0,%1,%2,%3}, {%4,%5,%6,%7}, {%8,%9}, {%0,%1,%2,%3};"
        : "+f"(c[0]), "+f"(c[1]), "+f"(c[2]), "+f"(c[3])
        : "r"(a[0]), "r"(a[1]), "r"(a[2]), "r"(a[3]), "r"(b0), "r"(b1));
}

#define LDP_ 72   // padded row length (bf16): 144B rows, 16B-aligned, LDSM conflict-free

template <int EPI>
__global__ void __launch_bounds__(256) hmma_kernel(
    const __nv_bfloat16* __restrict__ Abf,   // [M][ldk]
    const __nv_bfloat16* __restrict__ Bbf,   // [N][ldk]
    int ldk,
    const float* __restrict__ bias,
    __nv_bfloat16* __restrict__ outb, int ldob,
    float* __restrict__ outf, float2* __restrict__ part)
{
    __shared__ __nv_bfloat16 As[128 * LDP_];
    __shared__ __nv_bfloat16 Bs[128 * LDP_];
    const uint32_t sA = smem_u32(As), sB = smem_u32(Bs);
    const int tid = threadIdx.x, wid = tid >> 5, lane = tid & 31;
    const int m0 = blockIdx.y * 128, n0 = blockIdx.x * 128;
    const int mi = wid >> 1, nj = wid & 1;    // warp grid 4 (m) x 2 (n)
    const int qr = lane >> 2, qc = lane & 3;  // quad row / col-in-quad

    const int lrowA = lane & 15, lkA = (lane >> 4) * 8;
    const int lrowB = (lane & 7) + ((lane >> 4) << 3), lkB = ((lane >> 3) & 1) * 8;

    float acc[2][8][4];
#pragma unroll
    for (int ms = 0; ms < 2; ++ms)
#pragma unroll
        for (int ns = 0; ns < 8; ++ns)
#pragma unroll
            for (int q = 0; q < 4; ++q) acc[ms][ns][q] = 0.f;

    for (int k0 = 0; k0 < ldk; k0 += 64) {
#pragma unroll
        for (int i = 0; i < 4; ++i) {
            int u = tid + i * 256;
            int r = u >> 3, c = u & 7;             // 8 uint4 per 64-wide row
            *(uint4*)(As + r * LDP_ + c * 8) =
                *(const uint4*)(Abf + (size_t)(m0 + r) * ldk + k0 + c * 8);
            *(uint4*)(Bs + r * LDP_ + c * 8) =
                *(const uint4*)(Bbf + (size_t)(n0 + r) * ldk + k0 + c * 8);
        }
        __syncthreads();
#pragma unroll
        for (int kk = 0; kk < 64; kk += 16) {
            uint32_t a[2][4];
#pragma unroll
            for (int ms = 0; ms < 2; ++ms)
                ldsm4(a[ms][0], a[ms][1], a[ms][2], a[ms][3],
                      sA + (uint32_t)((mi * 32 + ms * 16 + lrowA) * LDP_ + kk + lkA) * 2);
            uint32_t bf[8][2];
#pragma unroll
            for (int np = 0; np < 4; ++np) {
                uint32_t r0, r1, r2, r3;
                ldsm4(r0, r1, r2, r3,
                      sB + (uint32_t)((nj * 64 + np * 16 + lrowB) * LDP_ + kk + lkB) * 2);
                bf[np * 2 + 0][0] = r0; bf[np * 2 + 0][1] = r1;
                bf[np * 2 + 1][0] = r2; bf[np * 2 + 1][1] = r3;
            }
#pragma unroll
            for (int ns = 0; ns < 8; ++ns) {
                mma16816(acc[0][ns], a[0], bf[ns][0], bf[ns][1]);
                mma16816(acc[1][ns], a[1], bf[ns][0], bf[ns][1]);
            }
        }
        __syncthreads();
    }

    const int colbase = n0 + nj * 64;
#pragma unroll
    for (int ms = 0; ms < 2; ++ms) {
#pragma unroll
        for (int half = 0; half < 2; ++half) {
            int row = m0 + mi * 32 + ms * 16 + half * 8 + qr;
            if (EPI == 0) {
                // tanh(acc + bias) -> bf16
#pragma unroll
                for (int ns = 0; ns < 8; ++ns) {
                    int col = colbase + ns * 8 + qc * 2;
                    float v0 = tanhf(acc[ms][ns][half * 2 + 0] + bias[col]);
                    float v1 = tanhf(acc[ms][ns][half * 2 + 1] + bias[col + 1]);
                    *(__nv_bfloat162*)(outb + (size_t)row * ldob + col) =
                        __floats2bfloat162_rn(v0, v1);
                }
            } else {
                float* op = outf + (size_t)row * V_ + colbase + qc * 2;
                float mx = -1e30f;
#pragma unroll
                for (int ns = 0; ns < 8; ++ns) {
                    float v0 = acc[ms][ns][half * 2 + 0];
                    float v1 = acc[ms][ns][half * 2 + 1];
                    *(float2*)(op + ns * 8) = make_float2(v0, v1);
                    mx = fmaxf(mx, fmaxf(v0, v1));
                }
                mx = fmaxf(mx, __shfl_xor_sync(0xffffffffu, mx, 1));
                mx = fmaxf(mx, __shfl_xor_sync(0xffffffffu, mx, 2));
                float sm = 0.f;
#pragma unroll
                for (int ns = 0; ns < 8; ++ns) {
                    sm += __expf(acc[ms][ns][half * 2 + 0] - mx);
                    sm += __expf(acc[ms][ns][half * 2 + 1] - mx);
                }
                sm += __shfl_xor_sync(0xffffffffu, sm, 1);
                sm += __shfl_xor_sync(0xffffffffu, sm, 2);
                if (qc == 0)
                    part[(size_t)row * NT2_ + blockIdx.x * 2 + nj] = make_float2(mx, sm);
            }
        }
    }
}

// ---------------- K6: combine per-tile softmax partials -> lse per row ----------------
__global__ void lse_kernel() {
    int row = blockIdx.x, lane = threadIdx.x;
    float m = -1e30f, s = 0.f;
    for (int i = lane; i < NT2_; i += 32) {
        float2 p = g_part[(size_t)row * NT2_ + i];
        if (p.x > m) { s = s * __expf(m - p.x) + p.y; m = p.x; }
        else         { s = s + p.y * __expf(p.x - m); }
    }
#pragma unroll
    for (int o = 16; o > 0; o >>= 1) {
        float mo = __shfl_xor_sync(0xffffffffu, m, o);
        float so = __shfl_xor_sync(0xffffffffu, s, o);
        if (mo > m) { s = s * __expf(m - mo) + so; m = mo; }
        else        { s = s + so * __expf(mo - m); }
    }
    if (lane == 0) g_lse[row] = m + logf(s);
}

// ---------------- K7: out = score - lse[row] ----------------
__global__ void sub_kernel(float* __restrict__ out) {
    size_t idx = (size_t)blockIdx.x * 256 + threadIdx.x;
    int row = (int)(idx / (V_ / 4));
    float4 v = ((float4*)out)[idx];
    float l = g_lse[row];
    v.x -= l; v.y -= l; v.z -= l; v.w -= l;
    ((float4*)out)[idx] = v;
}

// ---------------- launch (gemm1h is launch #4 -> gets profiled) ----------------
extern "C" void kernel_launch(void* const* d_in, const int* in_sizes, int n_in,
                              void* d_out, int out_size) {
    const int*   x     = (const int*)d_in[0];
    const float* emb_W = (const float*)d_in[1];
    const float* W_ih  = (const float*)d_in[2];
    const float* W_hh  = (const float*)d_in[3];
    const float* b_ih  = (const float*)d_in[4];
    const float* b_hh  = (const float*)d_in[5];
    const float* lin_W = (const float*)d_in[6];
    const float* lin_b = (const float*)d_in[7];
    float* out = (float*)d_out;

    float *feat, *gx;
    __nv_bfloat16 *featbf, *embh, *linbf, *logbf;
    float2* part;
    cudaGetSymbolAddress((void**)&feat,   g_feat);
    cudaGetSymbolAddress((void**)&featbf, g_featbf);
    cudaGetSymbolAddress((void**)&gx,     g_gx);
    cudaGetSymbolAddress((void**)&embh,   g_embh);
    cudaGetSymbolAddress((void**)&linbf,  g_linbf);
    cudaGetSymbolAddress((void**)&logbf,  g_logbf);
    cudaGetSymbolAddress((void**)&part,   g_part);

    // 1: fused prep (pack + embed + cvt emb + cvt linW)
    prep_kernel<<<PREP_BLOCKS, 256>>>(W_hh, x, emb_W, lin_W);
    // 2: gx = emb @ W_ih^T + b_ih (fp32 SIMT)
    gemm_kernel<<<dim3(G_ / 128, T_ / 128), 256>>>(feat + H_, F_, W_ih, E_, b_ih,
                                                   gx, G_, E_);
    // 3: GRU recurrence (fp32 state, bf16 feat out)
    gru_kernel<<<GRU_CTAS, 256>>>(x, b_hh);
    // 4: logits = tanh(featbf @ linbf^T + lin_b) -> bf16   [PROFILED]
    hmma_kernel<0><<<dim3(E_ / 128, T_ / 128), 256>>>(featbf, linbf, F_, lin_b,
                                                      logbf, E_, nullptr, nullptr);
    // 5: scores = logbf @ embh^T + fused softmax partials
    hmma_kernel<1><<<dim3(NT_, T_ / 128), 256>>>(logbf, embh, E_, nullptr,
                                                 nullptr, 0, out, part);
    // 6, 7: logsumexp combine + subtract
    lse_kernel<<<T_, 32>>>();
    sub_kernel<<<(T_ * (V_ / 4)) / 256, 256>>>(out);
}

// round 11
// speedup vs baseline: 1.3179x; 1.1996x over previous
#include <cuda_runtime.h>
#include <cuda_bf16.h>
#include <math.h>
#include <cstdint>

#define B_ 8
#define S_ 256
#define V_ 32000
#define E_ 512
#define H_ 1024
#define G_ 3072      // 3H
#define T_ 2048      // B*S
#define F_ 1536      // H+E
#define NT_ 250      // V/128 score tiles per row
#define NT2_ 500     // per-row softmax partials
#define GRU_CTAS 128

// ---------------- scratch (static device globals; no allocation) ----------------
__device__ float g_Wpack[(size_t)GRU_CTAS * 1024 * 32];  // per-CTA packed W_hh [c][k][g24(pad32)]
__device__ __nv_bfloat16 g_featbf[(size_t)T_ * F_];      // bf16 feat: ctx | emb
__device__ float g_gx[(size_t)T_ * G_];                  // input gates (fp32)
__device__ __nv_bfloat16 g_embh[(size_t)V_ * E_];        // emb table bf16
__device__ __nv_bfloat16 g_linbf[(size_t)E_ * F_];       // lin_W bf16
__device__ __nv_bfloat16 g_wihbf[(size_t)G_ * E_];       // W_ih bf16
__device__ __nv_bfloat16 g_logbf[(size_t)T_ * E_];       // logits bf16
__device__ float2 g_part[(size_t)T_ * NT2_];             // (max, sumexp) partials
__device__ float g_lse[T_];
__device__ float g_hbuf[2 * H_ * B_];                    // ping-pong hidden state [k][b] fp32
__device__ unsigned int g_cnt[S_];                       // per-step barrier counters

// ---------------- packed f32x2 helpers ----------------
__device__ __forceinline__ void fma2(uint64_t& c, uint64_t a, uint64_t b) {
    asm("fma.rn.f32x2 %0, %1, %2, %0;" : "+l"(c) : "l"(a), "l"(b));
}
__device__ __forceinline__ uint64_t pack_dup(float w) {
    uint64_t r;
    asm("mov.b64 %0, {%1, %1};" : "=l"(r) : "f"(w));
    return r;
}
__device__ __forceinline__ void unpack2(uint64_t v, float& lo, float& hi) {
    asm("mov.b64 {%0, %1}, %2;" : "=f"(lo), "=f"(hi) : "l"(v));
}
__device__ __forceinline__ uint32_t smem_u32(const void* p) {
    uint32_t a;
    asm("{ .reg .u64 t; cvta.to.shared.u64 t, %1; cvt.u32.u64 %0, t; }" : "=r"(a) : "l"(p));
    return a;
}
__device__ __forceinline__ void ldsm4(uint32_t& r0, uint32_t& r1, uint32_t& r2, uint32_t& r3,
                                      uint32_t addr) {
    asm volatile("ldmatrix.sync.aligned.m8n8.x4.shared.b16 {%0,%1,%2,%3}, [%4];"
                 : "=r"(r0), "=r"(r1), "=r"(r2), "=r"(r3) : "r"(addr));
}

// ---------------- K1: fused prep ----------------
#define PREP_EMBED0   GRU_CTAS                              // 128
#define PREP_CVTE0    (PREP_EMBED0 + T_)                    // 2176
#define PREP_CVTL0    (PREP_CVTE0 + (V_ * E_ / 4) / 256)    // 18176
#define PREP_CVTW0    (PREP_CVTL0 + (E_ * F_ / 4) / 256)    // 18944
#define PREP_BLOCKS   (PREP_CVTW0 + (G_ * E_ / 4) / 256)    // 20480

__global__ void __launch_bounds__(256) prep_kernel(
    const float* __restrict__ W_hh, const int* __restrict__ x,
    const float* __restrict__ emb_W, const float* __restrict__ lin_W,
    const float* __restrict__ W_ih)
{
    const int bid = blockIdx.x, tid = threadIdx.x;
    if (bid < PREP_EMBED0) {
        int c = bid;
        if (c == 0 && tid < S_) g_cnt[tid] = 0u;
        for (int idx = tid; idx < 1024 * 32; idx += 256) {
            int k = idx >> 5, g24 = idx & 31;
            float v = 0.f;
            if (g24 < 24) {
                int gate = g24 >> 3, jj = g24 & 7;
                int g = gate * H_ + c * 8 + jj;
                v = W_hh[(size_t)g * H_ + k];
            }
            g_Wpack[(size_t)c * 32768 + idx] = v;
        }
    } else if (bid < PREP_CVTE0) {
        int t = bid - PREP_EMBED0;
        if (tid < 128) {
            int tok = x[t];
            float4 v = ((const float4*)(emb_W + (size_t)tok * E_))[tid];
            __nv_bfloat162* d = (__nv_bfloat162*)(g_featbf + (size_t)t * F_ + H_) + 2 * tid;
            d[0] = __floats2bfloat162_rn(v.x, v.y);
            d[1] = __floats2bfloat162_rn(v.z, v.w);
        }
    } else if (bid < PREP_CVTL0) {
        int i = (bid - PREP_CVTE0) * 256 + tid;
        float4 v = ((const float4*)emb_W)[i];
        ((__nv_bfloat162*)g_embh)[2 * i]     = __floats2bfloat162_rn(v.x, v.y);
        ((__nv_bfloat162*)g_embh)[2 * i + 1] = __floats2bfloat162_rn(v.z, v.w);
    } else if (bid < PREP_CVTW0) {
        int i = (bid - PREP_CVTL0) * 256 + tid;
        float4 v = ((const float4*)lin_W)[i];
        ((__nv_bfloat162*)g_linbf)[2 * i]     = __floats2bfloat162_rn(v.x, v.y);
        ((__nv_bfloat162*)g_linbf)[2 * i + 1] = __floats2bfloat162_rn(v.z, v.w);
    } else {
        int i = (bid - PREP_CVTW0) * 256 + tid;
        float4 v = ((const float4*)W_ih)[i];
        ((__nv_bfloat162*)g_wihbf)[2 * i]     = __floats2bfloat162_rn(v.x, v.y);
        ((__nv_bfloat162*)g_wihbf)[2 * i + 1] = __floats2bfloat162_rn(v.z, v.w);
    }
}

// ---------------- K3: persistent GRU (384-thread GEMV) ----------------
__global__ void __launch_bounds__(384, 1) gru_kernel(const int* __restrict__ x,
                                                     const float* __restrict__ b_hh) {
    __shared__ float h_s[H_ * B_];          // 32 KB [k][b]
    __shared__ float red[24 * 16 * 8];      // 12 KB [g24][kc][b]
    __shared__ float gh_s[24 * 8];
    const int c = blockIdx.x, tid = threadIdx.x;
    const int j0 = c * 8;
    const int g24 = tid % 24, kc = tid / 24;   // kc in 0..15

    const int jj = tid >> 3, bb = tid & 7;
    const int j = j0 + jj;
    float bh0 = 0.f, bh1 = 0.f, bh2 = 0.f;
    if (tid < 64) { bh0 = b_hh[j]; bh1 = b_hh[H_ + j]; bh2 = b_hh[2 * H_ + j]; }

    unsigned int* cnt;
    {
        unsigned int* base;
        asm("mov.u64 %0, g_cnt;" : "=l"(base));
        cnt = base;
    }

    for (int s = 0; s < S_; ++s) {
        const int p = s & 1;

        float xr = 0.f, xz = 0.f, xn = 0.f;
        int msk = 0, tix = 0;
        if (tid < 64) {
            tix = bb * S_ + s;
            const float* gxr = g_gx + (size_t)tix * G_;
            xr = __ldcg(gxr + j);
            xz = __ldcg(gxr + H_ + j);
            xn = __ldcg(gxr + 2 * H_ + j);
            msk = (__ldg(x + tix) == 0);           // PAD
        }

        if (s == 0) {
            for (int i = tid; i < H_ * B_; i += 384) h_s[i] = 0.f;
        } else {
            const float4* src = (const float4*)(g_hbuf + p * H_ * B_);
            float4* dst = (float4*)h_s;
            for (int i = tid; i < H_ * B_ / 4; i += 384) dst[i] = __ldcg(src + i);
        }
        __syncthreads();

        {
            uint64_t a0 = 0ull, a1 = 0ull, a2 = 0ull, a3 = 0ull;
            const float* wp = g_Wpack + ((size_t)c * 1024 + kc * 64) * 32 + g24;
            const ulonglong2* h8 = (const ulonglong2*)h_s + kc * 64 * 2;
#pragma unroll 4
            for (int k = 0; k < 64; ++k) {
                uint64_t ww = pack_dup(wp[k * 32]);
                ulonglong2 u = h8[2 * k];
                ulonglong2 v = h8[2 * k + 1];
                fma2(a0, ww, u.x); fma2(a1, ww, u.y);
                fma2(a2, ww, v.x); fma2(a3, ww, v.y);
            }
            float* rp = red + (g24 * 16 + kc) * 8;
            unpack2(a0, rp[0], rp[1]);
            unpack2(a1, rp[2], rp[3]);
            unpack2(a2, rp[4], rp[5]);
            unpack2(a3, rp[6], rp[7]);
        }
        __syncthreads();
        if (tid < 192) {
            int gg = tid % 24, b = tid / 24;
            float v = 0.f;
#pragma unroll
            for (int q = 0; q < 16; ++q) v += red[(gg * 16 + q) * 8 + b];
            gh_s[gg * 8 + b] = v;
        }
        __syncthreads();
        if (tid < 64) {
            float hr = gh_s[(0 * 8 + jj) * 8 + bb] + bh0;
            float hz = gh_s[(1 * 8 + jj) * 8 + bb] + bh1;
            float hn = gh_s[(2 * 8 + jj) * 8 + bb] + bh2;
            float r = 1.f / (1.f + __expf(-(xr + hr)));
            float z = 1.f / (1.f + __expf(-(xz + hz)));
            float n = tanhf(xn + r * hn);
            float hold = h_s[j * 8 + bb];
            float hnew = (1.f - z) * n + z * hold;
            float hout = msk ? hold : hnew;
            g_hbuf[(p ^ 1) * H_ * B_ + j * 8 + bb] = hout;
            g_featbf[(size_t)tix * F_ + j] = __float2bfloat16(msk ? 0.f : hout);
        }
        if (s < S_ - 1) {
            __syncthreads();
            if (tid == 0) {
                asm volatile("red.release.gpu.global.add.u32 [%0], 1;"
                             :: "l"(cnt + s) : "memory");
                unsigned int v;
                do {
                    asm volatile("ld.acquire.gpu.global.u32 %0, [%1];"
                                 : "=r"(v) : "l"(cnt + s) : "memory");
                } while (v < (unsigned)GRU_CTAS);
            }
            __syncthreads();
        }
    }
}

// ---------------- HMMA bf16 GEMM template ----------------
// C = A[M,K(lda)] @ B[N,K(ldb)]^T
// EPI 0: tanh(acc+bias) -> bf16 out.  EPI 1: fp32 out + softmax partials.  EPI 2: acc+bias -> fp32 out.
__device__ __forceinline__ void mma16816(float* c, const uint32_t* a, uint32_t b0, uint32_t b1) {
    asm volatile(
        "mma.sync.aligned.m16n8k16.row.col.f32.bf16.bf16.f32 "
        "{%0,%1,%2,%3}, {%4,%5,%6,%7}, {%8,%9}, {%0,%1,%2,%3};"
        : "+f"(c[0]), "+f"(c[1]), "+f"(c[2]), "+f"(c[3])
        : "r"(a[0]), "r"(a[1]), "r"(a[2]), "r"(a[3]), "r"(b0), "r"(b1));
}

#define LDP_ 72   // padded row length (bf16): 144B rows, LDSM conflict-free

template <int EPI>
__global__ void __launch_bounds__(256) hmma_kernel(
    const __nv_bfloat16* __restrict__ Abf, int lda,
    const __nv_bfloat16* __restrict__ Bbf, int ldb, int K,
    const float* __restrict__ bias,
    __nv_bfloat16* __restrict__ outb, int ldob,
    float* __restrict__ outf, int ldof, float2* __restrict__ part)
{
    __shared__ __nv_bfloat16 As[128 * LDP_];
    __shared__ __nv_bfloat16 Bs[128 * LDP_];
    const uint32_t sA = smem_u32(As), sB = smem_u32(Bs);
    const int tid = threadIdx.x, wid = tid >> 5, lane = tid & 31;
    const int m0 = blockIdx.y * 128, n0 = blockIdx.x * 128;
    const int mi = wid >> 1, nj = wid & 1;
    const int qr = lane >> 2, qc = lane & 3;

    const int lrowA = lane & 15, lkA = (lane >> 4) * 8;
    const int lrowB = (lane & 7) + ((lane >> 4) << 3), lkB = ((lane >> 3) & 1) * 8;

    float acc[2][8][4];
#pragma unroll
    for (int ms = 0; ms < 2; ++ms)
#pragma unroll
        for (int ns = 0; ns < 8; ++ns)
#pragma unroll
            for (int q = 0; q < 4; ++q) acc[ms][ns][q] = 0.f;

    for (int k0 = 0; k0 < K; k0 += 64) {
#pragma unroll
        for (int i = 0; i < 4; ++i) {
            int u = tid + i * 256;
            int r = u >> 3, c = u & 7;
            *(uint4*)(As + r * LDP_ + c * 8) =
                *(const uint4*)(Abf + (size_t)(m0 + r) * lda + k0 + c * 8);
            *(uint4*)(Bs + r * LDP_ + c * 8) =
                *(const uint4*)(Bbf + (size_t)(n0 + r) * ldb + k0 + c * 8);
        }
        __syncthreads();
#pragma unroll
        for (int kk = 0; kk < 64; kk += 16) {
            uint32_t a[2][4];
#pragma unroll
            for (int ms = 0; ms < 2; ++ms)
                ldsm4(a[ms][0], a[ms][1], a[ms][2], a[ms][3],
                      sA + (uint32_t)((mi * 32 + ms * 16 + lrowA) * LDP_ + kk + lkA) * 2);
            uint32_t bf[8][2];
#pragma unroll
            for (int np = 0; np < 4; ++np) {
                uint32_t r0, r1, r2, r3;
                ldsm4(r0, r1, r2, r3,
                      sB + (uint32_t)((nj * 64 + np * 16 + lrowB) * LDP_ + kk + lkB) * 2);
                bf[np * 2 + 0][0] = r0; bf[np * 2 + 0][1] = r1;
                bf[np * 2 + 1][0] = r2; bf[np * 2 + 1][1] = r3;
            }
#pragma unroll
            for (int ns = 0; ns < 8; ++ns) {
                mma16816(acc[0][ns], a[0], bf[ns][0], bf[ns][1]);
                mma16816(acc[1][ns], a[1], bf[ns][0], bf[ns][1]);
            }
        }
        __syncthreads();
    }

    const int colbase = n0 + nj * 64;
#pragma unroll
    for (int ms = 0; ms < 2; ++ms) {
#pragma unroll
        for (int half = 0; half < 2; ++half) {
            int row = m0 + mi * 32 + ms * 16 + half * 8 + qr;
            if (EPI == 0) {
#pragma unroll
                for (int ns = 0; ns < 8; ++ns) {
                    int col = colbase + ns * 8 + qc * 2;
                    float v0 = tanhf(acc[ms][ns][half * 2 + 0] + bias[col]);
                    float v1 = tanhf(acc[ms][ns][half * 2 + 1] + bias[col + 1]);
                    *(__nv_bfloat162*)(outb + (size_t)row * ldob + col) =
                        __floats2bfloat162_rn(v0, v1);
                }
            } else if (EPI == 2) {
#pragma unroll
                for (int ns = 0; ns < 8; ++ns) {
                    int col = colbase + ns * 8 + qc * 2;
                    float v0 = acc[ms][ns][half * 2 + 0] + bias[col];
                    float v1 = acc[ms][ns][half * 2 + 1] + bias[col + 1];
                    *(float2*)(outf + (size_t)row * ldof + col) = make_float2(v0, v1);
                }
            } else {
                float* op = outf + (size_t)row * ldof + colbase + qc * 2;
                float mx = -1e30f;
#pragma unroll
                for (int ns = 0; ns < 8; ++ns) {
                    float v0 = acc[ms][ns][half * 2 + 0];
                    float v1 = acc[ms][ns][half * 2 + 1];
                    *(float2*)(op + ns * 8) = make_float2(v0, v1);
                    mx = fmaxf(mx, fmaxf(v0, v1));
                }
                mx = fmaxf(mx, __shfl_xor_sync(0xffffffffu, mx, 1));
                mx = fmaxf(mx, __shfl_xor_sync(0xffffffffu, mx, 2));
                float sm = 0.f;
#pragma unroll
                for (int ns = 0; ns < 8; ++ns) {
                    sm += __expf(acc[ms][ns][half * 2 + 0] - mx);
                    sm += __expf(acc[ms][ns][half * 2 + 1] - mx);
                }
                sm += __shfl_xor_sync(0xffffffffu, sm, 1);
                sm += __shfl_xor_sync(0xffffffffu, sm, 2);
                if (qc == 0)
                    part[(size_t)row * NT2_ + blockIdx.x * 2 + nj] = make_float2(mx, sm);
            }
        }
    }
}

// ---------------- K6: combine partials -> lse ----------------
__global__ void lse_kernel() {
    int row = blockIdx.x, lane = threadIdx.x;
    float m = -1e30f, s = 0.f;
    for (int i = lane; i < NT2_; i += 32) {
        float2 p = g_part[(size_t)row * NT2_ + i];
        if (p.x > m) { s = s * __expf(m - p.x) + p.y; m = p.x; }
        else         { s = s + p.y * __expf(p.x - m); }
    }
#pragma unroll
    for (int o = 16; o > 0; o >>= 1) {
        float mo = __shfl_xor_sync(0xffffffffu, m, o);
        float so = __shfl_xor_sync(0xffffffffu, s, o);
        if (mo > m) { s = s * __expf(m - mo) + so; m = mo; }
        else        { s = s + so * __expf(mo - m); }
    }
    if (lane == 0) g_lse[row] = m + logf(s);
}

// ---------------- K7: out -= lse[row] ----------------
__global__ void sub_kernel(float* __restrict__ out) {
    size_t idx = (size_t)blockIdx.x * 256 + threadIdx.x;
    int row = (int)(idx / (V_ / 4));
    float4 v = ((float4*)out)[idx];
    float l = g_lse[row];
    v.x -= l; v.y -= l; v.z -= l; v.w -= l;
    ((float4*)out)[idx] = v;
}

// ---------------- launch ----------------
extern "C" void kernel_launch(void* const* d_in, const int* in_sizes, int n_in,
                              void* d_out, int out_size) {
    const int*   x     = (const int*)d_in[0];
    const float* emb_W = (const float*)d_in[1];
    const float* W_ih  = (const float*)d_in[2];
    const float* W_hh  = (const float*)d_in[3];
    const float* b_ih  = (const float*)d_in[4];
    const float* b_hh  = (const float*)d_in[5];
    const float* lin_W = (const float*)d_in[6];
    const float* lin_b = (const float*)d_in[7];
    float* out = (float*)d_out;

    float* gx;
    __nv_bfloat16 *featbf, *embh, *linbf, *wihbf, *logbf;
    float2* part;
    cudaGetSymbolAddress((void**)&featbf, g_featbf);
    cudaGetSymbolAddress((void**)&gx,     g_gx);
    cudaGetSymbolAddress((void**)&embh,   g_embh);
    cudaGetSymbolAddress((void**)&linbf,  g_linbf);
    cudaGetSymbolAddress((void**)&wihbf,  g_wihbf);
    cudaGetSymbolAddress((void**)&logbf,  g_logbf);
    cudaGetSymbolAddress((void**)&part,   g_part);

    // 1: fused prep
    prep_kernel<<<PREP_BLOCKS, 256>>>(W_hh, x, emb_W, lin_W, W_ih);
    // 2: gx = emb_bf16 @ W_ih_bf16^T + b_ih  (HMMA, fp32 out)
    hmma_kernel<2><<<dim3(G_ / 128, T_ / 128), 256>>>(featbf + H_, F_, wihbf, E_, E_,
                                                      b_ih, nullptr, 0, gx, G_, nullptr);
    // 3: GRU recurrence
    gru_kernel<<<GRU_CTAS, 384>>>(x, b_hh);
    // 4: logits = tanh(featbf @ linbf^T + lin_b) -> bf16   [profiled]
    hmma_kernel<0><<<dim3(E_ / 128, T_ / 128), 256>>>(featbf, F_, linbf, F_, F_,
                                                      lin_b, logbf, E_, nullptr, 0, nullptr);
    // 5: scores + fused softmax partials
    hmma_kernel<1><<<dim3(NT_, T_ / 128), 256>>>(logbf, E_, embh, E_, E_,
                                                 nullptr, nullptr, 0, out, V_, part);
    // 6, 7
    lse_kernel<<<T_, 32>>>();
    sub_kernel<<<(T_ * (V_ / 4)) / 256, 256>>>(out);
}

// round 12
// speedup vs baseline: 2.6811x; 2.0343x over previous
#include <cuda_runtime.h>
#include <cuda_bf16.h>
#include <math.h>
#include <cstdint>

#define B_ 8
#define S_ 256
#define V_ 32000
#define E_ 512
#define H_ 1024
#define G_ 3072      // 3H
#define T_ 2048      // B*S
#define F_ 1536      // H+E
#define NT_ 250      // V/128 score tiles per row
#define NT2_ 500     // per-row softmax partials
#define GRU_CTAS 128
#define LDKW 516     // u32 words per batch row in h_s (1032 bf16, bank-spread)

// ---------------- scratch (static device globals; no allocation) ----------------
__device__ uint4 g_wfrag[(size_t)GRU_CTAS * 4096];       // W_hh bf16 MMA A-fragments, 64KB/CTA
__device__ __nv_bfloat16 g_featbf[(size_t)T_ * F_];      // bf16 feat: ctx | emb
__device__ float g_gx[(size_t)T_ * G_];                  // input gates (fp32)
__device__ __nv_bfloat16 g_embh[(size_t)V_ * E_];        // emb table bf16
__device__ __nv_bfloat16 g_linbf[(size_t)E_ * F_];       // lin_W bf16
__device__ __nv_bfloat16 g_wihbf[(size_t)G_ * E_];       // W_ih bf16
__device__ __nv_bfloat16 g_logbf[(size_t)T_ * E_];       // logits bf16
__device__ float2 g_part[(size_t)T_ * NT2_];             // (max, sumexp) partials
__device__ float g_lse[T_];
__device__ __nv_bfloat16 g_hbuf16[2 * B_ * H_];          // ping-pong h exchange, bf16 [b][k]
__device__ unsigned int g_cnt[S_];                       // per-step barrier counters

// ---------------- helpers ----------------
__device__ __forceinline__ uint32_t smem_u32(const void* p) {
    uint32_t a;
    asm("{ .reg .u64 t; cvta.to.shared.u64 t, %1; cvt.u32.u64 %0, t; }" : "=r"(a) : "l"(p));
    return a;
}
__device__ __forceinline__ void ldsm4(uint32_t& r0, uint32_t& r1, uint32_t& r2, uint32_t& r3,
                                      uint32_t addr) {
    asm volatile("ldmatrix.sync.aligned.m8n8.x4.shared.b16 {%0,%1,%2,%3}, [%4];"
                 : "=r"(r0), "=r"(r1), "=r"(r2), "=r"(r3) : "r"(addr));
}
__device__ __forceinline__ void mma16816(float* c, const uint32_t* a, uint32_t b0, uint32_t b1) {
    asm volatile(
        "mma.sync.aligned.m16n8k16.row.col.f32.bf16.bf16.f32 "
        "{%0,%1,%2,%3}, {%4,%5,%6,%7}, {%8,%9}, {%0,%1,%2,%3};"
        : "+f"(c[0]), "+f"(c[1]), "+f"(c[2]), "+f"(c[3])
        : "r"(a[0]), "r"(a[1]), "r"(a[2]), "r"(a[3]), "r"(b0), "r"(b1));
}

// ---------------- K1: fused prep ----------------
#define PREP_EMBED0   GRU_CTAS                              // 128
#define PREP_CVTE0    (PREP_EMBED0 + T_)                    // 2176
#define PREP_CVTL0    (PREP_CVTE0 + (V_ * E_ / 4) / 256)    // 18176
#define PREP_CVTW0    (PREP_CVTL0 + (E_ * F_ / 4) / 256)    // 18944
#define PREP_BLOCKS   (PREP_CVTW0 + (G_ * E_ / 4) / 256)    // 20480

__global__ void __launch_bounds__(256) prep_kernel(
    const float* __restrict__ W_hh, const int* __restrict__ x,
    const float* __restrict__ emb_W, const float* __restrict__ lin_W,
    const float* __restrict__ W_ih)
{
    const int bid = blockIdx.x, tid = threadIdx.x;
    if (bid < PREP_EMBED0) {
        // ---- pack W_hh into mma.m16n8k16 A-fragments (bf16) for CTA c ----
        int c = bid;
        if (c == 0 && tid < S_) g_cnt[tid] = 0u;
        for (int it = 0; it < 16; ++it) {
            int li = it * 256 + tid;              // uint4 index within this CTA's block
            int w = li >> 9, rest = li & 511;
            int t = rest >> 6, rest2 = rest & 63;
            int m = rest2 >> 5, lane = rest2 & 31;
            uint32_t qv[4];
#pragma unroll
            for (int q = 0; q < 4; ++q) {
                int r32 = m * 16 + (lane >> 2) + ((q & 1) ? 8 : 0);
                int k = w * 128 + t * 16 + (lane & 3) * 2 + ((q >= 2) ? 8 : 0);
                float v0 = 0.f, v1 = 0.f;
                if (r32 < 24) {
                    int gate = r32 >> 3, jj = r32 & 7;
                    const float* src = W_hh + (size_t)(gate * H_ + c * 8 + jj) * H_ + k;
                    v0 = src[0]; v1 = src[1];
                }
                __nv_bfloat162 pv = __floats2bfloat162_rn(v0, v1);
                qv[q] = *(uint32_t*)&pv;
            }
            g_wfrag[(size_t)c * 4096 + li] = make_uint4(qv[0], qv[1], qv[2], qv[3]);
        }
    } else if (bid < PREP_CVTE0) {
        int t = bid - PREP_EMBED0;
        if (tid < 128) {
            int tok = x[t];
            float4 v = ((const float4*)(emb_W + (size_t)tok * E_))[tid];
            __nv_bfloat162* d = (__nv_bfloat162*)(g_featbf + (size_t)t * F_ + H_) + 2 * tid;
            d[0] = __floats2bfloat162_rn(v.x, v.y);
            d[1] = __floats2bfloat162_rn(v.z, v.w);
        }
    } else if (bid < PREP_CVTL0) {
        int i = (bid - PREP_CVTE0) * 256 + tid;
        float4 v = ((const float4*)emb_W)[i];
        ((__nv_bfloat162*)g_embh)[2 * i]     = __floats2bfloat162_rn(v.x, v.y);
        ((__nv_bfloat162*)g_embh)[2 * i + 1] = __floats2bfloat162_rn(v.z, v.w);
    } else if (bid < PREP_CVTW0) {
        int i = (bid - PREP_CVTL0) * 256 + tid;
        float4 v = ((const float4*)lin_W)[i];
        ((__nv_bfloat162*)g_linbf)[2 * i]     = __floats2bfloat162_rn(v.x, v.y);
        ((__nv_bfloat162*)g_linbf)[2 * i + 1] = __floats2bfloat162_rn(v.z, v.w);
    } else {
        int i = (bid - PREP_CVTW0) * 256 + tid;
        float4 v = ((const float4*)W_ih)[i];
        ((__nv_bfloat162*)g_wihbf)[2 * i]     = __floats2bfloat162_rn(v.x, v.y);
        ((__nv_bfloat162*)g_wihbf)[2 * i + 1] = __floats2bfloat162_rn(v.z, v.w);
    }
}

// ---------------- K3: persistent GRU (HMMA GEMV, register-carried fp32 state) ----------------
__global__ void __launch_bounds__(256, 1) gru_kernel(const int* __restrict__ x,
                                                     const float* __restrict__ b_hh) {
    __shared__ uint32_t h_s[8 * LDKW];      // bf16x2 [b][k/2 padded] ~16.5KB
    __shared__ float red[8 * 32 * 8];       // [w][row32][b] 8KB
    __shared__ float gh_s[24 * 8];
    const int c = blockIdx.x, tid = threadIdx.x;
    const int w = tid >> 5, lane = tid & 31;
    const int j0 = c * 8;
    const int jj = tid >> 3, bb = tid & 7;  // gate threads (tid<64)
    const int j = j0 + jj;
    float bh0 = 0.f, bh1 = 0.f, bh2 = 0.f, hreg = 0.f;
    if (tid < 64) { bh0 = b_hh[j]; bh1 = b_hh[H_ + j]; bh2 = b_hh[2 * H_ + j]; }

    unsigned int* cnt;
    asm("mov.u64 %0, g_cnt;" : "=l"(cnt));
    const uint4* wf = g_wfrag + (size_t)c * 4096 + (w << 9) + lane;   // + (t*2+m)*32

    for (int s = 0; s < S_; ++s) {
        const int p = s & 1;

        // prefetch gx / mask (gate threads)
        float xr = 0.f, xz = 0.f, xn = 0.f;
        int msk = 0, tix = 0;
        if (tid < 64) {
            tix = bb * S_ + s;
            const float* gxr = g_gx + (size_t)tix * G_;
            xr = __ldcg(gxr + j);
            xz = __ldcg(gxr + H_ + j);
            xn = __ldcg(gxr + 2 * H_ + j);
            msk = (__ldg(x + tix) == 0);           // PAD
        }

        if (s == 0) {
            if (tid < 192) gh_s[tid] = 0.f;        // h == 0 -> gh == 0
            __syncthreads();
        } else {
            // load h (bf16) into padded smem
            const uint32_t* src = (const uint32_t*)g_hbuf16 + p * (8 * 512);
#pragma unroll
            for (int r = 0; r < 16; ++r) {
                int i = tid + r * 256;
                int b = i >> 9, kw = i & 511;
                h_s[b * LDKW + kw] = __ldcg(src + i);
            }
            __syncthreads();

            // HMMA GEMV: D[32 gates rows][8 b] partial over this warp's K slice (128)
            float acc[2][4] = {{0.f, 0.f, 0.f, 0.f}, {0.f, 0.f, 0.f, 0.f}};
            const uint32_t* hb = h_s + (lane >> 2) * LDKW + w * 64 + (lane & 3);
#pragma unroll
            for (int t = 0; t < 8; ++t) {
                uint32_t b0 = hb[t * 8];
                uint32_t b1 = hb[t * 8 + 4];
                uint4 a0 = wf[(t * 2 + 0) * 32];
                uint4 a1 = wf[(t * 2 + 1) * 32];
                uint32_t A0[4] = {a0.x, a0.y, a0.z, a0.w};
                uint32_t A1[4] = {a1.x, a1.y, a1.z, a1.w};
                mma16816(acc[0], A0, b0, b1);
                mma16816(acc[1], A1, b0, b1);
            }
            {
                int row = lane >> 2, col = (lane & 3) * 2;
                float* base = red + (size_t)w * 256;
                *(float2*)(base + (row +  0) * 8 + col) = make_float2(acc[0][0], acc[0][1]);
                *(float2*)(base + (row +  8) * 8 + col) = make_float2(acc[0][2], acc[0][3]);
                *(float2*)(base + (row + 16) * 8 + col) = make_float2(acc[1][0], acc[1][1]);
                *(float2*)(base + (row + 24) * 8 + col) = make_float2(acc[1][2], acc[1][3]);
            }
            __syncthreads();
            if (tid < 192) {
                int r = tid % 24, b = tid / 24;
                float v = 0.f;
#pragma unroll
                for (int q = 0; q < 8; ++q) v += red[(q * 32 + r) * 8 + b];
                gh_s[r * 8 + b] = v;
            }
            __syncthreads();
        }

        if (tid < 64) {
            float hr = gh_s[(0 * 8 + jj) * 8 + bb] + bh0;
            float hz = gh_s[(1 * 8 + jj) * 8 + bb] + bh1;
            float hn = gh_s[(2 * 8 + jj) * 8 + bb] + bh2;
            float r = 1.f / (1.f + __expf(-(xr + hr)));
            float z = 1.f / (1.f + __expf(-(xz + hz)));
            float n = tanhf(xn + r * hn);
            float hnew = (1.f - z) * n + z * hreg;
            float hout = msk ? hreg : hnew;
            hreg = hout;                                         // fp32 state in register
            g_hbuf16[(p ^ 1) * (B_ * H_) + bb * H_ + j] = __float2bfloat16(hout);
            g_featbf[(size_t)tix * F_ + j] = __float2bfloat16(msk ? 0.f : hout);
        }
        if (s < S_ - 1) {
            __syncthreads();
            if (tid == 0) {
                asm volatile("red.release.gpu.global.add.u32 [%0], 1;"
                             :: "l"(cnt + s) : "memory");
                unsigned int v;
                do {
                    asm volatile("ld.acquire.gpu.global.u32 %0, [%1];"
                                 : "=r"(v) : "l"(cnt + s) : "memory");
                } while (v < (unsigned)GRU_CTAS);
            }
            __syncthreads();
        }
    }
}

// ---------------- HMMA bf16 GEMM template ----------------
// C = A[M,K(lda)] @ B[N,K(ldb)]^T
// EPI 0: tanh(acc+bias)->bf16.  EPI 1: fp32 + softmax partials.  EPI 2: acc+bias->fp32.
#define LDP_ 72   // padded row length (bf16): 144B rows, LDSM conflict-free

template <int EPI>
__global__ void __launch_bounds__(256) hmma_kernel(
    const __nv_bfloat16* __restrict__ Abf, int lda,
    const __nv_bfloat16* __restrict__ Bbf, int ldb, int K,
    const float* __restrict__ bias,
    __nv_bfloat16* __restrict__ outb, int ldob,
    float* __restrict__ outf, int ldof, float2* __restrict__ part)
{
    __shared__ __nv_bfloat16 As[128 * LDP_];
    __shared__ __nv_bfloat16 Bs[128 * LDP_];
    const uint32_t sA = smem_u32(As), sB = smem_u32(Bs);
    const int tid = threadIdx.x, wid = tid >> 5, lane = tid & 31;
    const int m0 = blockIdx.y * 128, n0 = blockIdx.x * 128;
    const int mi = wid >> 1, nj = wid & 1;
    const int qr = lane >> 2, qc = lane & 3;

    const int lrowA = lane & 15, lkA = (lane >> 4) * 8;
    const int lrowB = (lane & 7) + ((lane >> 4) << 3), lkB = ((lane >> 3) & 1) * 8;

    float acc[2][8][4];
#pragma unroll
    for (int ms = 0; ms < 2; ++ms)
#pragma unroll
        for (int ns = 0; ns < 8; ++ns)
#pragma unroll
            for (int q = 0; q < 4; ++q) acc[ms][ns][q] = 0.f;

    for (int k0 = 0; k0 < K; k0 += 64) {
#pragma unroll
        for (int i = 0; i < 4; ++i) {
            int u = tid + i * 256;
            int r = u >> 3, c = u & 7;
            *(uint4*)(As + r * LDP_ + c * 8) =
                *(const uint4*)(Abf + (size_t)(m0 + r) * lda + k0 + c * 8);
            *(uint4*)(Bs + r * LDP_ + c * 8) =
                *(const uint4*)(Bbf + (size_t)(n0 + r) * ldb + k0 + c * 8);
        }
        __syncthreads();
#pragma unroll
        for (int kk = 0; kk < 64; kk += 16) {
            uint32_t a[2][4];
#pragma unroll
            for (int ms = 0; ms < 2; ++ms)
                ldsm4(a[ms][0], a[ms][1], a[ms][2], a[ms][3],
                      sA + (uint32_t)((mi * 32 + ms * 16 + lrowA) * LDP_ + kk + lkA) * 2);
            uint32_t bf[8][2];
#pragma unroll
            for (int np = 0; np < 4; ++np) {
                uint32_t r0, r1, r2, r3;
                ldsm4(r0, r1, r2, r3,
                      sB + (uint32_t)((nj * 64 + np * 16 + lrowB) * LDP_ + kk + lkB) * 2);
                bf[np * 2 + 0][0] = r0; bf[np * 2 + 0][1] = r1;
                bf[np * 2 + 1][0] = r2; bf[np * 2 + 1][1] = r3;
            }
#pragma unroll
            for (int ns = 0; ns < 8; ++ns) {
                mma16816(acc[0][ns], a[0], bf[ns][0], bf[ns][1]);
                mma16816(acc[1][ns], a[1], bf[ns][0], bf[ns][1]);
            }
        }
        __syncthreads();
    }

    const int colbase = n0 + nj * 64;
#pragma unroll
    for (int ms = 0; ms < 2; ++ms) {
#pragma unroll
        for (int half = 0; half < 2; ++half) {
            int row = m0 + mi * 32 + ms * 16 + half * 8 + qr;
            if (EPI == 0) {
#pragma unroll
                for (int ns = 0; ns < 8; ++ns) {
                    int col = colbase + ns * 8 + qc * 2;
                    float v0 = tanhf(acc[ms][ns][half * 2 + 0] + bias[col]);
                    float v1 = tanhf(acc[ms][ns][half * 2 + 1] + bias[col + 1]);
                    *(__nv_bfloat162*)(outb + (size_t)row * ldob + col) =
                        __floats2bfloat162_rn(v0, v1);
                }
            } else if (EPI == 2) {
#pragma unroll
                for (int ns = 0; ns < 8; ++ns) {
                    int col = colbase + ns * 8 + qc * 2;
                    float v0 = acc[ms][ns][half * 2 + 0] + bias[col];
                    float v1 = acc[ms][ns][half * 2 + 1] + bias[col + 1];
                    *(float2*)(outf + (size_t)row * ldof + col) = make_float2(v0, v1);
                }
            } else {
                float* op = outf + (size_t)row * ldof + colbase + qc * 2;
                float mx = -1e30f;
#pragma unroll
                for (int ns = 0; ns < 8; ++ns) {
                    float v0 = acc[ms][ns][half * 2 + 0];
                    float v1 = acc[ms][ns][half * 2 + 1];
                    *(float2*)(op + ns * 8) = make_float2(v0, v1);
                    mx = fmaxf(mx, fmaxf(v0, v1));
                }
                mx = fmaxf(mx, __shfl_xor_sync(0xffffffffu, mx, 1));
                mx = fmaxf(mx, __shfl_xor_sync(0xffffffffu, mx, 2));
                float sm = 0.f;
#pragma unroll
                for (int ns = 0; ns < 8; ++ns) {
                    sm += __expf(acc[ms][ns][half * 2 + 0] - mx);
                    sm += __expf(acc[ms][ns][half * 2 + 1] - mx);
                }
                sm += __shfl_xor_sync(0xffffffffu, sm, 1);
                sm += __shfl_xor_sync(0xffffffffu, sm, 2);
                if (qc == 0)
                    part[(size_t)row * NT2_ + blockIdx.x * 2 + nj] = make_float2(mx, sm);
            }
        }
    }
}

// ---------------- K6: combine partials -> lse ----------------
__global__ void lse_kernel() {
    int row = blockIdx.x, lane = threadIdx.x;
    float m = -1e30f, s = 0.f;
    for (int i = lane; i < NT2_; i += 32) {
        float2 p = g_part[(size_t)row * NT2_ + i];
        if (p.x > m) { s = s * __expf(m - p.x) + p.y; m = p.x; }
        else         { s = s + p.y * __expf(p.x - m); }
    }
#pragma unroll
    for (int o = 16; o > 0; o >>= 1) {
        float mo = __shfl_xor_sync(0xffffffffu, m, o);
        float so = __shfl_xor_sync(0xffffffffu, s, o);
        if (mo > m) { s = s * __expf(m - mo) + so; m = mo; }
        else        { s = s + so * __expf(mo - m); }
    }
    if (lane == 0) g_lse[row] = m + logf(s);
}

// ---------------- K7: out -= lse[row] ----------------
__global__ void sub_kernel(float* __restrict__ out) {
    size_t idx = (size_t)blockIdx.x * 256 + threadIdx.x;
    int row = (int)(idx / (V_ / 4));
    float4 v = ((float4*)out)[idx];
    float l = g_lse[row];
    v.x -= l; v.y -= l; v.z -= l; v.w -= l;
    ((float4*)out)[idx] = v;
}

// ---------------- launch ----------------
extern "C" void kernel_launch(void* const* d_in, const int* in_sizes, int n_in,
                              void* d_out, int out_size) {
    const int*   x     = (const int*)d_in[0];
    const float* emb_W = (const float*)d_in[1];
    const float* W_ih  = (const float*)d_in[2];
    const float* W_hh  = (const float*)d_in[3];
    const float* b_ih  = (const float*)d_in[4];
    const float* b_hh  = (const float*)d_in[5];
    const float* lin_W = (const float*)d_in[6];
    const float* lin_b = (const float*)d_in[7];
    float* out = (float*)d_out;

    float* gx;
    __nv_bfloat16 *featbf, *embh, *linbf, *wihbf, *logbf;
    float2* part;
    cudaGetSymbolAddress((void**)&featbf, g_featbf);
    cudaGetSymbolAddress((void**)&gx,     g_gx);
    cudaGetSymbolAddress((void**)&embh,   g_embh);
    cudaGetSymbolAddress((void**)&linbf,  g_linbf);
    cudaGetSymbolAddress((void**)&wihbf,  g_wihbf);
    cudaGetSymbolAddress((void**)&logbf,  g_logbf);
    cudaGetSymbolAddress((void**)&part,   g_part);

    // 1: fused prep (pack W_hh fragments + embed + cvt tables)
    prep_kernel<<<PREP_BLOCKS, 256>>>(W_hh, x, emb_W, lin_W, W_ih);
    // 2: gx = emb_bf16 @ W_ih_bf16^T + b_ih  (HMMA, fp32 out)
    hmma_kernel<2><<<dim3(G_ / 128, T_ / 128), 256>>>(featbf + H_, F_, wihbf, E_, E_,
                                                      b_ih, nullptr, 0, gx, G_, nullptr);
    // 3: GRU recurrence (HMMA GEMV, fp32 register state, bf16 h exchange)
    gru_kernel<<<GRU_CTAS, 256>>>(x, b_hh);
    // 4: logits = tanh(featbf @ linbf^T + lin_b) -> bf16   [profiled]
    hmma_kernel<0><<<dim3(E_ / 128, T_ / 128), 256>>>(featbf, F_, linbf, F_, F_,
                                                      lin_b, logbf, E_, nullptr, 0, nullptr);
    // 5: scores + fused softmax partials
    hmma_kernel<1><<<dim3(NT_, T_ / 128), 256>>>(logbf, E_, embh, E_, E_,
                                                 nullptr, nullptr, 0, out, V_, part);
    // 6, 7
    lse_kernel<<<T_, 32>>>();
    sub_kernel<<<(T_ * (V_ / 4)) / 256, 256>>>(out);
}